// round 5
// baseline (speedup 1.0000x reference)
#include <cuda_runtime.h>
#include <cuda_bf16.h>
#include <math.h>

// ---------------- problem constants ----------------
#define DD      128      // node feat dim
#define HH      256      // hidden = 2*D
#define MAXN    8192
#define NB      64       // batches
#define RP      132      // padded row stride for Ht (RP*4 bytes = 528 = 33*16, float4-aligned)
#define NTHR    512

// scratch (global __device__ arrays: sanctioned, no cudaMalloc)
__device__ float g_messages[2ull * MAXN * HH];   // 16 MB
__device__ float g_att[2ull * MAXN * DD];        // 8 MB
__device__ float g_colmeans[2 * DD];
__device__ int   g_seg[2 * NB * 2];

#define TILE_F   (16*128)
#define SMEM_FLOATS (256*RP + 2*TILE_F + 2*TILE_F)
#define SMEM_BYTES  (SMEM_FLOATS*4 + 256*4)

// ---------------- async copy helpers ----------------
__device__ __forceinline__ void cp_async16(unsigned int saddr, const void* gptr) {
    asm volatile("cp.async.cg.shared.global [%0], [%1], 16;" :: "r"(saddr), "l"(gptr));
}
__device__ __forceinline__ void cp_commit() {
    asm volatile("cp.async.commit_group;");
}
__device__ __forceinline__ void cp_wait0() {
    asm volatile("cp.async.wait_group 0;");
}
__device__ __forceinline__ void red_add_v4(float* p, float a, float b, float c, float d) {
    asm volatile("red.global.add.v4.f32 [%0], {%1,%2,%3,%4};"
                 :: "l"(p), "f"(a), "f"(b), "f"(c), "f"(d) : "memory");
}

// ---------------- tiny setup kernels ----------------
__global__ void zero_msgs_kernel(int n4) {
    int i = blockIdx.x * blockDim.x + threadIdx.x;
    if (i < n4) ((float4*)g_messages)[i] = make_float4(0.f, 0.f, 0.f, 0.f);
}

__global__ void seg_kernel(const int* __restrict__ b1,
                           const int* __restrict__ b2, int N) {
    int t = threadIdx.x;
    if (t >= 2 * NB) return;
    int g = t / NB;
    int b = t % NB;
    const int* arr = g ? b2 : b1;
    int lo = 0, hi = N;
    while (lo < hi) { int mid = (lo + hi) >> 1; if (arr[mid] < b) lo = mid + 1; else hi = mid; }
    int start = lo;
    lo = 0; hi = N;
    while (lo < hi) { int mid = (lo + hi) >> 1; if (arr[mid] <= b) lo = mid + 1; else hi = mid; }
    g_seg[t * 2 + 0] = start;
    g_seg[t * 2 + 1] = lo;
}

__global__ void colmean_kernel(const float* __restrict__ x1,
                               const float* __restrict__ x2, int N) {
    const float* x = blockIdx.x ? x2 : x1;
    int c = threadIdx.x;   // 0..127
    float s0 = 0.f, s1 = 0.f, s2 = 0.f, s3 = 0.f;
    int r = 0;
    for (; r + 3 < N; r += 4) {
        s0 += x[(size_t)(r + 0) * DD + c];
        s1 += x[(size_t)(r + 1) * DD + c];
        s2 += x[(size_t)(r + 2) * DD + c];
        s3 += x[(size_t)(r + 3) * DD + c];
    }
    for (; r < N; ++r) s0 += x[(size_t)r * DD + c];
    g_colmeans[blockIdx.x * DD + c] = (s0 + s1 + s2 + s3) * (1.f / (float)N);
}

// ---------------- f32x2 micro-kernel (4x8 per thread, 512 threads) ----------------
// A tile: [16][astride] k-major; thread owns rows ty*4..+3 (one broadcast LDS.128)
// W tile: [16][128] split-half: Wtile[k*128 + h*64 + tx*4 + q] holds col tx*8 + h*4 + q
// c2[i][j]: packed (cols 2j,2j+1) for row ty*4+i
__device__ __forceinline__ void mma16_f32x2(
    const float* __restrict__ Atile, int astride,
    const float* __restrict__ Wtile,
    int ty, int tx, unsigned long long c2[4][4])
{
    #pragma unroll
    for (int k = 0; k < 16; ++k) {
        float4 t0 = *(const float4*)(Atile + k * astride + ty * 4);
        ulonglong2 u0 = *(const ulonglong2*)(Wtile + k * 128 + tx * 4);
        ulonglong2 u1 = *(const ulonglong2*)(Wtile + k * 128 + 64 + tx * 4);
        unsigned long long b2[4];
        b2[0] = u0.x; b2[1] = u0.y; b2[2] = u1.x; b2[3] = u1.y;
        unsigned int ar[4];
        ar[0]=__float_as_uint(t0.x); ar[1]=__float_as_uint(t0.y);
        ar[2]=__float_as_uint(t0.z); ar[3]=__float_as_uint(t0.w);
        unsigned long long a2[4];
        #pragma unroll
        for (int i = 0; i < 4; i++)
            asm("mov.b64 %0, {%1, %1};" : "=l"(a2[i]) : "r"(ar[i]));
        #pragma unroll
        for (int i = 0; i < 4; i++)
            #pragma unroll
            for (int j = 0; j < 4; j++)
                asm("fma.rn.f32x2 %0, %1, %2, %0;"
                    : "+l"(c2[i][j]) : "l"(a2[i]), "l"(b2[j]));
    }
}

__device__ __forceinline__ void unpack2(unsigned long long v, float& lo, float& hi) {
    unsigned int l, h;
    asm("mov.b64 {%0, %1}, %2;" : "=r"(l), "=r"(h) : "l"(v));
    lo = __uint_as_float(l); hi = __uint_as_float(h);
}

// W tile loader: each of 512 threads does ONE cp.async16
// wk = tid>>5 (k row 0..15), wi = tid&31: h = wi>>4, wt = wi&15
__device__ __forceinline__ void cp_w(unsigned int ws_saddr, int buf, int wk, int h, int wt,
                                     const float* __restrict__ wrow /* row wk of tile, col0 of 128-block */) {
    unsigned int s = ws_saddr + (unsigned int)((buf * TILE_F + wk * 128 + h * 64 + wt * 4) * 4);
    cp_async16(s, wrow + wt * 8 + h * 4);
}

// A tile loader: each thread loads float4 and scatters 4 transposed scalars
__device__ __forceinline__ void sts_a4(float* Ab, int lk0, int lr, float4 a0) {
    Ab[(lk0 + 0) * 128 + lr] = a0.x;
    Ab[(lk0 + 1) * 128 + lr] = a0.y;
    Ab[(lk0 + 2) * 128 + lr] = a0.z;
    Ab[(lk0 + 3) * 128 + lr] = a0.w;
}

// ---------------- fused message MLP + scatter ----------------
__global__ void __launch_bounds__(NTHR, 1)
msg_kernel(const float* __restrict__ x1, const float* __restrict__ x2,
           const int* __restrict__ ei1, const int* __restrict__ ei2,
           const float* __restrict__ W1, const float* __restrict__ b1,
           const float* __restrict__ W2, const float* __restrict__ b2,
           int N, int E) {
    int g = blockIdx.y;
    const float* x = g ? x2 : x1;
    const int* ei = g ? ei2 : ei1;
    float* messages = g_messages + (size_t)g * N * HH;

    extern __shared__ float sm[];
    float* Ht = sm;                        // [256][RP]
    float* As = Ht + 256 * RP;             // [2][16*128]
    float* Ws = As + 2 * TILE_F;           // [2][16*128]
    int*   s_src = (int*)(Ws + 2 * TILE_F);
    int*   s_tgt = s_src + 128;
    unsigned int ws_saddr = (unsigned int)__cvta_generic_to_shared(Ws);

    int tid = threadIdx.x;
    int base = blockIdx.x * 128;

    if (tid < 128) {
        int e = base + tid;
        s_tgt[tid] = (e < E) ? ei[e] : 0;
        s_src[tid] = (e < E) ? ei[E + e] : 0;
    }
    __syncthreads();

    int ty = tid >> 4, tx = tid & 15;             // compute mapping (32 x 16)
    int lr = tid & 127, lk0 = (tid >> 7) * 4;     // A loader: row, k-offset {0,4,8,12}
    int wk = tid >> 5, wh = (tid >> 4) & 1, wt = tid & 15;  // W loader

    // ---------- stage A: H = relu([x_src|x_tgt] @ W1 + b1) ----------
    for (int nh = 0; nh < 2; ++nh) {
        unsigned long long c2[4][4];
        #pragma unroll
        for (int i = 0; i < 4; i++)
            #pragma unroll
            for (int j = 0; j < 4; j++) c2[i][j] = 0ull;

        // preload kt = 0
        {
            cp_w(ws_saddr, 0, wk, wh, wt, W1 + (size_t)wk * HH + nh * 128);
            cp_commit();
            int kk = lk0;  // < 16 -> src
            int node = s_src[lr];
            float4 a0 = *(const float4*)(x + (size_t)node * DD + kk);
            sts_a4(As, lk0, lr, a0);
            cp_wait0();
        }
        __syncthreads();

        for (int kt = 0; kt < 16; ++kt) {
            int cur = kt & 1;
            float4 a0;
            bool pf = (kt + 1 < 16);
            if (pf) {
                int kk = (kt + 1) * 16 + lk0;
                int node = (kk < 128) ? s_src[lr] : s_tgt[lr];
                a0 = *(const float4*)(x + (size_t)node * DD + (kk & 127));
                cp_w(ws_saddr, cur ^ 1, wk, wh, wt,
                     W1 + (size_t)((kt + 1) * 16 + wk) * HH + nh * 128);
                cp_commit();
            }
            mma16_f32x2(As + cur * TILE_F, 128, Ws + cur * TILE_F, ty, tx, c2);
            if (pf) sts_a4(As + (cur ^ 1) * TILE_F, lk0, lr, a0);
            cp_wait0();
            __syncthreads();
        }

        // epilogue: bias + relu -> Ht[n][r]
        #pragma unroll
        for (int j = 0; j < 4; ++j) {
            int n0 = nh * 128 + tx * 8 + 2 * j;
            float bj0 = b1[n0], bj1 = b1[n0 + 1];
            #pragma unroll
            for (int i = 0; i < 4; ++i) {
                float lo, hi; unpack2(c2[i][j], lo, hi);
                Ht[n0 * RP + ty * 4 + i]       = fmaxf(lo + bj0, 0.f);
                Ht[(n0 + 1) * RP + ty * 4 + i] = fmaxf(hi + bj1, 0.f);
            }
        }
        __syncthreads();
    }

    // ---------- stage B: M = H @ W2 + b2 ; scatter-add ----------
    for (int nh = 0; nh < 2; ++nh) {
        unsigned long long c2[4][4];
        #pragma unroll
        for (int i = 0; i < 4; i++)
            #pragma unroll
            for (int j = 0; j < 4; j++) c2[i][j] = 0ull;

        cp_w(ws_saddr, 0, wk, wh, wt, W2 + (size_t)wk * HH + nh * 128);
        cp_commit();
        cp_wait0();
        __syncthreads();

        for (int kt = 0; kt < 16; ++kt) {
            int cur = kt & 1;
            bool pf = (kt + 1 < 16);
            if (pf) {
                cp_w(ws_saddr, cur ^ 1, wk, wh, wt,
                     W2 + (size_t)((kt + 1) * 16 + wk) * HH + nh * 128);
                cp_commit();
            }
            mma16_f32x2(Ht + kt * 16 * RP, RP, Ws + cur * TILE_F, ty, tx, c2);
            cp_wait0();
            __syncthreads();
        }

        // epilogue: vectorized scatter-add into messages[tgt]
        float bb[8];
        #pragma unroll
        for (int q = 0; q < 8; q++) bb[q] = b2[nh * 128 + tx * 8 + q];
        #pragma unroll
        for (int i = 0; i < 4; i++) {
            int r = ty * 4 + i;
            if (base + r < E) {
                int node = s_tgt[r];
                float* mrow = messages + (size_t)node * HH + nh * 128 + tx * 8;
                float v[8];
                #pragma unroll
                for (int j = 0; j < 4; j++) {
                    float lo, hi; unpack2(c2[i][j], lo, hi);
                    v[2 * j] = lo + bb[2 * j];
                    v[2 * j + 1] = hi + bb[2 * j + 1];
                }
                red_add_v4(mrow,     v[0], v[1], v[2], v[3]);
                red_add_v4(mrow + 4, v[4], v[5], v[6], v[7]);
            }
        }
        __syncthreads();
    }
}

// ---------------- block-diagonal cross attention ----------------
__global__ void attn_kernel(const float* __restrict__ x1,
                            const float* __restrict__ x2, int N) {
    int b = blockIdx.x;
    int dir = blockIdx.y;
    const float* rowsrc = dir ? x2 : x1;
    const float* colsrc = dir ? x1 : x2;
    float* att = g_att + (size_t)dir * N * DD;
    int rs = g_seg[(dir * NB + b) * 2 + 0];
    int re = g_seg[(dir * NB + b) * 2 + 1];
    int cs = g_seg[((1 - dir) * NB + b) * 2 + 0];
    int ce = g_seg[((1 - dir) * NB + b) * 2 + 1];
    const float* mean = g_colmeans + (1 - dir) * DD;

    int warp = threadIdx.x >> 5, lane = threadIdx.x & 31;

    for (int i = rs + warp; i < re; i += 8) {
        float4 a = *(const float4*)(rowsrc + (size_t)i * DD + lane * 4);
        float4 res;
        if (cs == ce) {
            float4 mv = *(const float4*)(mean + lane * 4);
            res.x = a.x - mv.x; res.y = a.y - mv.y;
            res.z = a.z - mv.z; res.w = a.w - mv.w;
        } else {
            float m = -3.4e38f;
            for (int j = cs; j < ce; ++j) {
                float4 bv = *(const float4*)(colsrc + (size_t)j * DD + lane * 4);
                float d = a.x * bv.x + a.y * bv.y + a.z * bv.z + a.w * bv.w;
                #pragma unroll
                for (int o = 16; o; o >>= 1) d += __shfl_xor_sync(0xffffffffu, d, o);
                m = fmaxf(m, d);
            }
            float se = 0.f;
            float4 acc = make_float4(0.f, 0.f, 0.f, 0.f);
            for (int j = cs; j < ce; ++j) {
                float4 bv = *(const float4*)(colsrc + (size_t)j * DD + lane * 4);
                float d = a.x * bv.x + a.y * bv.y + a.z * bv.z + a.w * bv.w;
                #pragma unroll
                for (int o = 16; o; o >>= 1) d += __shfl_xor_sync(0xffffffffu, d, o);
                float w = __expf(d - m);
                se += w;
                acc.x = fmaf(w, bv.x, acc.x);
                acc.y = fmaf(w, bv.y, acc.y);
                acc.z = fmaf(w, bv.z, acc.z);
                acc.w = fmaf(w, bv.w, acc.w);
            }
            float inv = 1.f / se;
            res.x = a.x - acc.x * inv; res.y = a.y - acc.y * inv;
            res.z = a.z - acc.z * inv; res.w = a.w - acc.w * inv;
        }
        *(float4*)(att + (size_t)i * DD + lane * 4) = res;
    }
}

// ---------------- fused node update MLP ----------------
__global__ void __launch_bounds__(NTHR, 1)
upd_kernel(const float* __restrict__ x1, const float* __restrict__ x2,
           const float* __restrict__ W1u, const float* __restrict__ b1u,
           const float* __restrict__ W2u, const float* __restrict__ b2u,
           float* __restrict__ out, int N) {
    int g = blockIdx.y;
    const float* x = g ? x2 : x1;
    const float* messages = g_messages + (size_t)g * N * HH;
    const float* att = g_att + (size_t)g * N * DD;
    float* o = out + (size_t)g * N * DD;

    extern __shared__ float sm[];
    float* Ht = sm;
    float* As = Ht + 256 * RP;
    float* Ws = As + 2 * TILE_F;
    unsigned int ws_saddr = (unsigned int)__cvta_generic_to_shared(Ws);

    int tid = threadIdx.x;
    int base = blockIdx.x * 128;
    int ty = tid >> 4, tx = tid & 15;
    int lr = tid & 127, lk0 = (tid >> 7) * 4;
    int wk = tid >> 5, wh = (tid >> 4) & 1, wt = tid & 15;

    int mynode = base + lr;
    if (mynode >= N) mynode = N - 1;
    const float* rowm = messages + (size_t)mynode * HH;
    const float* rowa = att + (size_t)mynode * DD;
    const float* rowx = x + (size_t)mynode * DD;

    // ---------- stage 1: K = 512, u = [msg|att|x] ----------
    for (int nh = 0; nh < 2; ++nh) {
        unsigned long long c2[4][4];
        #pragma unroll
        for (int i = 0; i < 4; i++)
            #pragma unroll
            for (int j = 0; j < 4; j++) c2[i][j] = 0ull;

        {
            cp_w(ws_saddr, 0, wk, wh, wt, W1u + (size_t)wk * HH + nh * 128);
            cp_commit();
            float4 a0 = *(const float4*)(rowm + lk0);   // kt=0 -> messages
            sts_a4(As, lk0, lr, a0);
            cp_wait0();
        }
        __syncthreads();

        for (int kt = 0; kt < 32; ++kt) {
            int cur = kt & 1;
            float4 a0;
            bool pf = (kt + 1 < 32);
            if (pf) {
                int kk = (kt + 1) * 16 + lk0;
                const float* src;
                int col;
                if (kk < 256)      { src = rowm; col = kk; }
                else if (kk < 384) { src = rowa; col = kk - 256; }
                else               { src = rowx; col = kk - 384; }
                a0 = *(const float4*)(src + col);
                cp_w(ws_saddr, cur ^ 1, wk, wh, wt,
                     W1u + (size_t)((kt + 1) * 16 + wk) * HH + nh * 128);
                cp_commit();
            }
            mma16_f32x2(As + cur * TILE_F, 128, Ws + cur * TILE_F, ty, tx, c2);
            if (pf) sts_a4(As + (cur ^ 1) * TILE_F, lk0, lr, a0);
            cp_wait0();
            __syncthreads();
        }

        #pragma unroll
        for (int j = 0; j < 4; ++j) {
            int n0 = nh * 128 + tx * 8 + 2 * j;
            float bj0 = b1u[n0], bj1 = b1u[n0 + 1];
            #pragma unroll
            for (int i = 0; i < 4; ++i) {
                float lo, hi; unpack2(c2[i][j], lo, hi);
                Ht[n0 * RP + ty * 4 + i]       = fmaxf(lo + bj0, 0.f);
                Ht[(n0 + 1) * RP + ty * 4 + i] = fmaxf(hi + bj1, 0.f);
            }
        }
        __syncthreads();
    }

    // ---------- stage 2: out = x + Ht(128x256) @ W2u(256x128) + b2u ----------
    {
        unsigned long long c2[4][4];
        #pragma unroll
        for (int i = 0; i < 4; i++)
            #pragma unroll
            for (int j = 0; j < 4; j++) c2[i][j] = 0ull;

        cp_w(ws_saddr, 0, wk, wh, wt, W2u + (size_t)wk * DD);
        cp_commit();
        cp_wait0();
        __syncthreads();

        for (int kt = 0; kt < 16; ++kt) {
            int cur = kt & 1;
            bool pf = (kt + 1 < 16);
            if (pf) {
                cp_w(ws_saddr, cur ^ 1, wk, wh, wt, W2u + (size_t)((kt + 1) * 16 + wk) * DD);
                cp_commit();
            }
            mma16_f32x2(Ht + kt * 16 * RP, RP, Ws + cur * TILE_F, ty, tx, c2);
            cp_wait0();
            __syncthreads();
        }

        #pragma unroll
        for (int i = 0; i < 4; i++) {
            int node = base + ty * 4 + i;
            if (node < N) {
                int col = tx * 8;
                float4 r0, r1;
                float lo, hi;
                unpack2(c2[i][0], lo, hi);
                r0.x = lo + b2u[col + 0] + x[(size_t)node * DD + col + 0];
                r0.y = hi + b2u[col + 1] + x[(size_t)node * DD + col + 1];
                unpack2(c2[i][1], lo, hi);
                r0.z = lo + b2u[col + 2] + x[(size_t)node * DD + col + 2];
                r0.w = hi + b2u[col + 3] + x[(size_t)node * DD + col + 3];
                unpack2(c2[i][2], lo, hi);
                r1.x = lo + b2u[col + 4] + x[(size_t)node * DD + col + 4];
                r1.y = hi + b2u[col + 5] + x[(size_t)node * DD + col + 5];
                unpack2(c2[i][3], lo, hi);
                r1.z = lo + b2u[col + 6] + x[(size_t)node * DD + col + 6];
                r1.w = hi + b2u[col + 7] + x[(size_t)node * DD + col + 7];
                *(float4*)(o + (size_t)node * DD + col) = r0;
                *(float4*)(o + (size_t)node * DD + col + 4) = r1;
            }
        }
    }
}

// ---------------- launcher ----------------
extern "C" void kernel_launch(void* const* d_in, const int* in_sizes, int n_in,
                              void* d_out, int out_size) {
    const float* x1   = (const float*)d_in[0];
    const int*   ei1  = (const int*)d_in[1];
    const int*   bat1 = (const int*)d_in[2];
    const float* x2   = (const float*)d_in[3];
    const int*   ei2  = (const int*)d_in[4];
    const int*   bat2 = (const int*)d_in[5];
    const float* mW1 = (const float*)d_in[6];
    const float* mb1 = (const float*)d_in[7];
    const float* mW2 = (const float*)d_in[8];
    const float* mb2 = (const float*)d_in[9];
    const float* uW1 = (const float*)d_in[10];
    const float* ub1 = (const float*)d_in[11];
    const float* uW2 = (const float*)d_in[12];
    const float* ub2 = (const float*)d_in[13];
    float* out = (float*)d_out;

    int N = in_sizes[2];          // nodes per graph
    int E = in_sizes[1] / 2;      // edges per graph

    cudaFuncSetAttribute(msg_kernel, cudaFuncAttributeMaxDynamicSharedMemorySize, SMEM_BYTES);
    cudaFuncSetAttribute(upd_kernel, cudaFuncAttributeMaxDynamicSharedMemorySize, SMEM_BYTES);

    int zn4 = 2 * N * HH / 4;
    zero_msgs_kernel<<<(zn4 + 255) / 256, 256>>>(zn4);
    seg_kernel<<<1, 128>>>(bat1, bat2, N);
    colmean_kernel<<<2, DD>>>(x1, x2, N);

    dim3 mgrid((E + 127) / 128, 2);
    msg_kernel<<<mgrid, NTHR, SMEM_BYTES>>>(x1, x2, ei1, ei2, mW1, mb1, mW2, mb2, N, E);

    attn_kernel<<<dim3(NB, 2), 256>>>(x1, x2, N);

    dim3 ugrid((N + 127) / 128, 2);
    upd_kernel<<<ugrid, NTHR, SMEM_BYTES>>>(x1, x2, uW1, ub1, uW2, ub2, out, N);
}

// round 7
// speedup vs baseline: 1.8693x; 1.8693x over previous
#include <cuda_runtime.h>
#include <cuda_bf16.h>
#include <math.h>
#include <stdint.h>

// ---------------- problem constants ----------------
#define DD      128      // node feat dim
#define HH      256      // hidden = 2*D
#define MAXN    8192
#define NB      64       // batches
#define RP      132      // padded row stride for Ht (upd kernel)

// scratch (global __device__ arrays: sanctioned, no cudaMalloc)
__device__ float g_messages[2ull * MAXN * HH];   // 16 MB
__device__ float g_att[2ull * MAXN * DD];        // 8 MB
__device__ float g_colmeans[2 * DD];
__device__ int   g_seg[2 * NB * 2];
// pre-split W1/W2 as padded bf16 tiles: [layer][k-chunk][hi/lo][256 n x 136 k bf16]
#define WT_BYTES 69632            // 256 * 272
__device__ __align__(16) unsigned char g_wtile[2][2][2][WT_BYTES];

// ---------------- PTX helpers ----------------
__device__ __forceinline__ uint32_t smem_u32(const void* p) {
    uint32_t a;
    asm("{ .reg .u64 t; cvta.to.shared.u64 t, %1; cvt.u32.u64 %0, t; }" : "=r"(a) : "l"(p));
    return a;
}
__device__ __forceinline__ void cp_async16(unsigned int saddr, const void* gptr) {
    asm volatile("cp.async.cg.shared.global [%0], [%1], 16;" :: "r"(saddr), "l"(gptr));
}
__device__ __forceinline__ void cp_commit() { asm volatile("cp.async.commit_group;"); }
__device__ __forceinline__ void cp_wait0()  { asm volatile("cp.async.wait_group 0;"); }
__device__ __forceinline__ void red_add_v2(float* p, float a, float b) {
    asm volatile("red.global.add.v2.f32 [%0], {%1,%2};" :: "l"(p), "f"(a), "f"(b) : "memory");
}
__device__ __forceinline__ void red_add_v4(float* p, float a, float b, float c, float d) {
    asm volatile("red.global.add.v4.f32 [%0], {%1,%2,%3,%4};"
                 :: "l"(p), "f"(a), "f"(b), "f"(c), "f"(d) : "memory");
}
__device__ __forceinline__ void ldmx4(uint32_t r[4], uint32_t addr) {
    asm volatile("ldmatrix.sync.aligned.m8n8.x4.shared.b16 {%0,%1,%2,%3}, [%4];"
        : "=r"(r[0]), "=r"(r[1]), "=r"(r[2]), "=r"(r[3]) : "r"(addr));
}
__device__ __forceinline__ void mma_bf16(float d[4], const uint32_t a[4],
                                         uint32_t b0, uint32_t b1) {
    asm volatile("mma.sync.aligned.m16n8k16.row.col.f32.bf16.bf16.f32 "
        "{%0,%1,%2,%3}, {%4,%5,%6,%7}, {%8,%9}, {%0,%1,%2,%3};"
        : "+f"(d[0]), "+f"(d[1]), "+f"(d[2]), "+f"(d[3])
        : "r"(a[0]), "r"(a[1]), "r"(a[2]), "r"(a[3]), "r"(b0), "r"(b1));
}
__device__ __forceinline__ uint32_t pk(__nv_bfloat16 a, __nv_bfloat16 b) {
    __nv_bfloat162 t = __halves2bfloat162(a, b);
    return *reinterpret_cast<uint32_t*>(&t);
}

// ---------------- tiny setup kernels ----------------
__global__ void zero_msgs_kernel(int n4) {
    int i = blockIdx.x * blockDim.x + threadIdx.x;
    if (i < n4) ((float4*)g_messages)[i] = make_float4(0.f, 0.f, 0.f, 0.f);
}

__global__ void seg_kernel(const int* __restrict__ b1, const int* __restrict__ b2, int N) {
    int t = threadIdx.x;
    if (t >= 2 * NB) return;
    int g = t / NB, b = t % NB;
    const int* arr = g ? b2 : b1;
    int lo = 0, hi = N;
    while (lo < hi) { int m = (lo + hi) >> 1; if (arr[m] < b) lo = m + 1; else hi = m; }
    int start = lo;
    lo = 0; hi = N;
    while (lo < hi) { int m = (lo + hi) >> 1; if (arr[m] <= b) lo = m + 1; else hi = m; }
    g_seg[t * 2 + 0] = start;
    g_seg[t * 2 + 1] = lo;
}

__global__ void colmean_kernel(const float* __restrict__ x1, const float* __restrict__ x2, int N) {
    const float* x = blockIdx.x ? x2 : x1;
    int c = threadIdx.x;
    float s0 = 0.f, s1 = 0.f, s2 = 0.f, s3 = 0.f;
    int r = 0;
    for (; r + 3 < N; r += 4) {
        s0 += x[(size_t)(r + 0) * DD + c];
        s1 += x[(size_t)(r + 1) * DD + c];
        s2 += x[(size_t)(r + 2) * DD + c];
        s3 += x[(size_t)(r + 3) * DD + c];
    }
    for (; r < N; ++r) s0 += x[(size_t)r * DD + c];
    g_colmeans[blockIdx.x * DD + c] = (s0 + s1 + s2 + s3) * (1.f / (float)N);
}

// W (k-major [256k][256n]) -> W^T padded bf16 hi/lo tiles [n][k%128]
__global__ void prep_w_kernel(const float* __restrict__ W1, const float* __restrict__ W2) {
    int layer = blockIdx.y;
    int idx = blockIdx.x * 256 + threadIdx.x;   // k*256 + n
    int k = idx >> 8, n = idx & 255;
    const float* W = layer ? W2 : W1;
    float w = W[idx];
    __nv_bfloat16 h = __float2bfloat16(w);
    __nv_bfloat16 l = __float2bfloat16(w - __bfloat162float(h));
    int chunk = k >> 7, kl = k & 127;
    size_t off = (size_t)n * 272 + (size_t)kl * 2;
    *(__nv_bfloat16*)(g_wtile[layer][chunk][0] + off) = h;
    *(__nv_bfloat16*)(g_wtile[layer][chunk][1] + off) = l;
}

// ---------------- mma.sync message MLP + scatter ----------------
// SMEM: A_hi [64][136]bf16 (17408B), A_lo, B_hi [256][136]bf16 (69632B), B_lo, ids
#define OFF_AH 0
#define OFF_AL 17408
#define OFF_BH 34816
#define OFF_BL 104448
#define OFF_ID 174080
#define MSG_SMEM (174080 + 1024)

__global__ void __launch_bounds__(512, 1)
msg_mma_kernel(const float* __restrict__ x1, const float* __restrict__ x2,
               const int* __restrict__ ei1, const int* __restrict__ ei2,
               const float* __restrict__ b1, const float* __restrict__ b2,
               int N, int E) {
    int g = blockIdx.y;
    const float* x = g ? x2 : x1;
    const int* ei = g ? ei2 : ei1;
    float* messages = g_messages + (size_t)g * N * HH;

    extern __shared__ char smc[];
    uint32_t sb = smem_u32(smc);
    int* s_src = (int*)(smc + OFF_ID);
    int* s_tgt = s_src + 64;

    int tid = threadIdx.x, wid = tid >> 5, lane = tid & 31;
    int base = blockIdx.x * 64;

    if (tid < 64) {
        int e = base + tid;
        s_tgt[tid] = (e < E) ? ei[e] : 0;
        s_src[tid] = (e < E) ? ei[E + e] : 0;
    }
    __syncthreads();

    int wm = wid & 1;        // row block: 32*wm
    int wn = wid >> 1;       // col block: 32*wn  (0..7)
    int gr = lane >> 2, gc = lane & 3;   // mma D/C frag coords

    float acc[2][4][4];
    #pragma unroll
    for (int mt = 0; mt < 2; ++mt)
        #pragma unroll
        for (int nt = 0; nt < 4; ++nt)
            #pragma unroll
            for (int q = 0; q < 4; ++q) acc[mt][nt][q] = 0.f;

    // ================= layer 1: H = relu([x_src|x_tgt] @ W1 + b1) =================
    for (int c = 0; c < 2; ++c) {
        // B chunk (hi+lo) via cp.async, whole padded tile linearly
        {
            const unsigned char* hsrc = g_wtile[0][c][0];
            const unsigned char* lsrc = g_wtile[0][c][1];
            for (int t = tid; t < WT_BYTES / 16; t += 512) {
                cp_async16(sb + OFF_BH + t * 16, hsrc + t * 16);
                cp_async16(sb + OFF_BL + t * 16, lsrc + t * 16);
            }
            cp_commit();
        }
        // A chunk: gather + bf16 hi/lo split (8 threads per row, 16 cols each)
        {
            int r = tid >> 3, seg = tid & 7;
            int node = c ? s_tgt[r] : s_src[r];
            const float4* row = (const float4*)(x + (size_t)node * DD + seg * 16);
            uint32_t hi[8], lo[8];
            #pragma unroll
            for (int q = 0; q < 4; ++q) {
                float4 v = row[q];
                __nv_bfloat16 h0 = __float2bfloat16(v.x), h1 = __float2bfloat16(v.y);
                __nv_bfloat16 h2 = __float2bfloat16(v.z), h3 = __float2bfloat16(v.w);
                hi[q * 2 + 0] = pk(h0, h1);
                hi[q * 2 + 1] = pk(h2, h3);
                lo[q * 2 + 0] = pk(__float2bfloat16(v.x - __bfloat162float(h0)),
                                   __float2bfloat16(v.y - __bfloat162float(h1)));
                lo[q * 2 + 1] = pk(__float2bfloat16(v.z - __bfloat162float(h2)),
                                   __float2bfloat16(v.w - __bfloat162float(h3)));
            }
            uint4* dh = (uint4*)(smc + OFF_AH + r * 272 + seg * 32);
            uint4* dl = (uint4*)(smc + OFF_AL + r * 272 + seg * 32);
            dh[0] = make_uint4(hi[0], hi[1], hi[2], hi[3]);
            dh[1] = make_uint4(hi[4], hi[5], hi[6], hi[7]);
            dl[0] = make_uint4(lo[0], lo[1], lo[2], lo[3]);
            dl[1] = make_uint4(lo[4], lo[5], lo[6], lo[7]);
        }
        cp_wait0();
        __syncthreads();

        #pragma unroll
        for (int ks = 0; ks < 8; ++ks) {
            int k0 = ks * 16;
            uint32_t ah[2][4], al[2][4];
            #pragma unroll
            for (int mt = 0; mt < 2; ++mt) {
                int row = wm * 32 + mt * 16 + (lane & 15);
                uint32_t addr = sb + OFF_AH + row * 272 + (k0 + (lane >> 4) * 8) * 2;
                ldmx4(ah[mt], addr);
                ldmx4(al[mt], addr + (OFF_AL - OFF_AH));
            }
            uint32_t bh[2][4], bl[2][4];
            #pragma unroll
            for (int ntp = 0; ntp < 2; ++ntp) {
                int q = lane >> 3, rr = lane & 7;
                int n = wn * 32 + ntp * 16 + (q >> 1) * 8 + rr;
                int kk = k0 + (q & 1) * 8;
                uint32_t addr = sb + OFF_BH + n * 272 + kk * 2;
                ldmx4(bh[ntp], addr);
                ldmx4(bl[ntp], addr + (OFF_BL - OFF_BH));
            }
            #pragma unroll
            for (int mt = 0; mt < 2; ++mt)
                #pragma unroll
                for (int nt = 0; nt < 4; ++nt) {
                    int p = nt >> 1, h2 = (nt & 1) * 2;
                    mma_bf16(acc[mt][nt], ah[mt], bh[p][h2], bh[p][h2 + 1]);
                    mma_bf16(acc[mt][nt], ah[mt], bl[p][h2], bl[p][h2 + 1]);
                    mma_bf16(acc[mt][nt], al[mt], bh[p][h2], bh[p][h2 + 1]);
                }
        }
        __syncthreads();
    }

    // bias + relu + split into packed bf16 register fragments
    uint32_t hh[2][4][2], hl[2][4][2];
    #pragma unroll
    for (int nt = 0; nt < 4; ++nt) {
        int col = wn * 32 + nt * 8 + 2 * gc;
        float2 bv = *(const float2*)(b1 + col);
        #pragma unroll
        for (int mt = 0; mt < 2; ++mt) {
            float f0 = fmaxf(acc[mt][nt][0] + bv.x, 0.f);
            float f1 = fmaxf(acc[mt][nt][1] + bv.y, 0.f);
            float f2 = fmaxf(acc[mt][nt][2] + bv.x, 0.f);
            float f3 = fmaxf(acc[mt][nt][3] + bv.y, 0.f);
            __nv_bfloat16 h0 = __float2bfloat16(f0), h1 = __float2bfloat16(f1);
            __nv_bfloat16 h2 = __float2bfloat16(f2), h3 = __float2bfloat16(f3);
            hh[mt][nt][0] = pk(h0, h1);
            hh[mt][nt][1] = pk(h2, h3);
            hl[mt][nt][0] = pk(__float2bfloat16(f0 - __bfloat162float(h0)),
                               __float2bfloat16(f1 - __bfloat162float(h1)));
            hl[mt][nt][1] = pk(__float2bfloat16(f2 - __bfloat162float(h2)),
                               __float2bfloat16(f3 - __bfloat162float(h3)));
            // reset accumulator for layer 2
            acc[mt][nt][0] = acc[mt][nt][1] = acc[mt][nt][2] = acc[mt][nt][3] = 0.f;
        }
    }

    // ================= layer 2: M = H @ W2 + b2 =================
    for (int c = 0; c < 2; ++c) {
        {
            const unsigned char* hsrc = g_wtile[1][c][0];
            const unsigned char* lsrc = g_wtile[1][c][1];
            for (int t = tid; t < WT_BYTES / 16; t += 512) {
                cp_async16(sb + OFF_BH + t * 16, hsrc + t * 16);
                cp_async16(sb + OFF_BL + t * 16, lsrc + t * 16);
            }
            cp_commit();
        }
        // warps owning this H chunk write their fragments into the A tile
        if ((wn >> 2) == c) {
            #pragma unroll
            for (int mt = 0; mt < 2; ++mt) {
                int r = wm * 32 + mt * 16 + gr;
                #pragma unroll
                for (int nt = 0; nt < 4; ++nt) {
                    int cc = (wn & 3) * 32 + nt * 8 + 2 * gc;
                    *(uint32_t*)(smc + OFF_AH + r * 272 + cc * 2)       = hh[mt][nt][0];
                    *(uint32_t*)(smc + OFF_AL + r * 272 + cc * 2)       = hl[mt][nt][0];
                    *(uint32_t*)(smc + OFF_AH + (r + 8) * 272 + cc * 2) = hh[mt][nt][1];
                    *(uint32_t*)(smc + OFF_AL + (r + 8) * 272 + cc * 2) = hl[mt][nt][1];
                }
            }
        }
        cp_wait0();
        __syncthreads();

        #pragma unroll
        for (int ks = 0; ks < 8; ++ks) {
            int k0 = ks * 16;
            uint32_t ah[2][4], al[2][4];
            #pragma unroll
            for (int mt = 0; mt < 2; ++mt) {
                int row = wm * 32 + mt * 16 + (lane & 15);
                uint32_t addr = sb + OFF_AH + row * 272 + (k0 + (lane >> 4) * 8) * 2;
                ldmx4(ah[mt], addr);
                ldmx4(al[mt], addr + (OFF_AL - OFF_AH));
            }
            uint32_t bh[2][4], bl[2][4];
            #pragma unroll
            for (int ntp = 0; ntp < 2; ++ntp) {
                int q = lane >> 3, rr = lane & 7;
                int n = wn * 32 + ntp * 16 + (q >> 1) * 8 + rr;
                int kk = k0 + (q & 1) * 8;
                uint32_t addr = sb + OFF_BH + n * 272 + kk * 2;
                ldmx4(bh[ntp], addr);
                ldmx4(bl[ntp], addr + (OFF_BL - OFF_BH));
            }
            #pragma unroll
            for (int mt = 0; mt < 2; ++mt)
                #pragma unroll
                for (int nt = 0; nt < 4; ++nt) {
                    int p = nt >> 1, h2 = (nt & 1) * 2;
                    mma_bf16(acc[mt][nt], ah[mt], bh[p][h2], bh[p][h2 + 1]);
                    mma_bf16(acc[mt][nt], ah[mt], bl[p][h2], bl[p][h2 + 1]);
                    mma_bf16(acc[mt][nt], al[mt], bh[p][h2], bh[p][h2 + 1]);
                }
        }
        __syncthreads();
    }

    // ================= epilogue: scatter-add into messages[tgt] =================
    #pragma unroll
    for (int mt = 0; mt < 2; ++mt) {
        int r0 = wm * 32 + mt * 16 + gr;
        int r1 = r0 + 8;
        bool v0 = (base + r0) < E, v1 = (base + r1) < E;
        float* m0 = messages + (size_t)s_tgt[r0] * HH;
        float* m1 = messages + (size_t)s_tgt[r1] * HH;
        #pragma unroll
        for (int nt = 0; nt < 4; ++nt) {
            int col = wn * 32 + nt * 8 + 2 * gc;
            float2 bv = *(const float2*)(b2 + col);
            if (v0) red_add_v2(m0 + col, acc[mt][nt][0] + bv.x, acc[mt][nt][1] + bv.y);
            if (v1) red_add_v2(m1 + col, acc[mt][nt][2] + bv.x, acc[mt][nt][3] + bv.y);
        }
    }
}

// ---------------- block-diagonal cross attention (unchanged) ----------------
__global__ void attn_kernel(const float* __restrict__ x1,
                            const float* __restrict__ x2, int N) {
    int b = blockIdx.x;
    int dir = blockIdx.y;
    const float* rowsrc = dir ? x2 : x1;
    const float* colsrc = dir ? x1 : x2;
    float* att = g_att + (size_t)dir * N * DD;
    int rs = g_seg[(dir * NB + b) * 2 + 0];
    int re = g_seg[(dir * NB + b) * 2 + 1];
    int cs = g_seg[((1 - dir) * NB + b) * 2 + 0];
    int ce = g_seg[((1 - dir) * NB + b) * 2 + 1];
    const float* mean = g_colmeans + (1 - dir) * DD;

    int warp = threadIdx.x >> 5, lane = threadIdx.x & 31;

    for (int i = rs + warp; i < re; i += 8) {
        float4 a = *(const float4*)(rowsrc + (size_t)i * DD + lane * 4);
        float4 res;
        if (cs == ce) {
            float4 mv = *(const float4*)(mean + lane * 4);
            res.x = a.x - mv.x; res.y = a.y - mv.y;
            res.z = a.z - mv.z; res.w = a.w - mv.w;
        } else {
            float m = -3.4e38f;
            for (int j = cs; j < ce; ++j) {
                float4 bv = *(const float4*)(colsrc + (size_t)j * DD + lane * 4);
                float d = a.x * bv.x + a.y * bv.y + a.z * bv.z + a.w * bv.w;
                #pragma unroll
                for (int o = 16; o; o >>= 1) d += __shfl_xor_sync(0xffffffffu, d, o);
                m = fmaxf(m, d);
            }
            float se = 0.f;
            float4 acc = make_float4(0.f, 0.f, 0.f, 0.f);
            for (int j = cs; j < ce; ++j) {
                float4 bv = *(const float4*)(colsrc + (size_t)j * DD + lane * 4);
                float d = a.x * bv.x + a.y * bv.y + a.z * bv.z + a.w * bv.w;
                #pragma unroll
                for (int o = 16; o; o >>= 1) d += __shfl_xor_sync(0xffffffffu, d, o);
                float w = __expf(d - m);
                se += w;
                acc.x = fmaf(w, bv.x, acc.x);
                acc.y = fmaf(w, bv.y, acc.y);
                acc.z = fmaf(w, bv.z, acc.z);
                acc.w = fmaf(w, bv.w, acc.w);
            }
            float inv = 1.f / se;
            res.x = a.x - acc.x * inv; res.y = a.y - acc.y * inv;
            res.z = a.z - acc.z * inv; res.w = a.w - acc.w * inv;
        }
        *(float4*)(att + (size_t)i * DD + lane * 4) = res;
    }
}

// ---------------- fused node update MLP (round-4 SIMT version) ----------------
#define TILE_F   (16*128)
#define UPD_SMEM ((256*RP + 2*TILE_F + 2*TILE_F)*4 + 256*4)

__device__ __forceinline__ void mma16_f32x2(
    const float* __restrict__ Atile, int astride,
    const float* __restrict__ Wtile,
    int ty, int tx, unsigned long long c2[8][4])
{
    #pragma unroll
    for (int k = 0; k < 16; ++k) {
        float4 t0 = *(const float4*)(Atile + k * astride + ty * 8);
        float4 t1 = *(const float4*)(Atile + k * astride + ty * 8 + 4);
        ulonglong2 u0 = *(const ulonglong2*)(Wtile + k * 128 + tx * 4);
        ulonglong2 u1 = *(const ulonglong2*)(Wtile + k * 128 + 64 + tx * 4);
        unsigned long long b2v[4];
        b2v[0] = u0.x; b2v[1] = u0.y; b2v[2] = u1.x; b2v[3] = u1.y;
        unsigned int ar[8];
        ar[0]=__float_as_uint(t0.x); ar[1]=__float_as_uint(t0.y);
        ar[2]=__float_as_uint(t0.z); ar[3]=__float_as_uint(t0.w);
        ar[4]=__float_as_uint(t1.x); ar[5]=__float_as_uint(t1.y);
        ar[6]=__float_as_uint(t1.z); ar[7]=__float_as_uint(t1.w);
        unsigned long long a2[8];
        #pragma unroll
        for (int i = 0; i < 8; i++)
            asm("mov.b64 %0, {%1, %1};" : "=l"(a2[i]) : "r"(ar[i]));
        #pragma unroll
        for (int i = 0; i < 8; i++)
            #pragma unroll
            for (int j = 0; j < 4; j++)
                asm("fma.rn.f32x2 %0, %1, %2, %0;"
                    : "+l"(c2[i][j]) : "l"(a2[i]), "l"(b2v[j]));
    }
}
__device__ __forceinline__ void unpack2(unsigned long long v, float& lo, float& hi) {
    unsigned int l, h;
    asm("mov.b64 {%0, %1}, %2;" : "=r"(l), "=r"(h) : "l"(v));
    lo = __uint_as_float(l); hi = __uint_as_float(h);
}
__device__ __forceinline__ void cp_w(unsigned int ws_saddr, int buf, int wk, int w16,
                                     const float* __restrict__ wrow) {
    unsigned int s = ws_saddr + (unsigned int)((buf * TILE_F + wk * 128 + w16 * 4) * 4);
    cp_async16(s,          wrow + w16 * 8);
    cp_async16(s + 64 * 4, wrow + w16 * 8 + 4);
}
__device__ __forceinline__ void sts_a(float* Ab, int lk0, int lr, float4 a0, float4 a1) {
    Ab[(lk0 + 0) * 128 + lr] = a0.x; Ab[(lk0 + 1) * 128 + lr] = a0.y;
    Ab[(lk0 + 2) * 128 + lr] = a0.z; Ab[(lk0 + 3) * 128 + lr] = a0.w;
    Ab[(lk0 + 4) * 128 + lr] = a1.x; Ab[(lk0 + 5) * 128 + lr] = a1.y;
    Ab[(lk0 + 6) * 128 + lr] = a1.z; Ab[(lk0 + 7) * 128 + lr] = a1.w;
}

__global__ void __launch_bounds__(256, 1)
upd_kernel(const float* __restrict__ x1, const float* __restrict__ x2,
           const float* __restrict__ W1u, const float* __restrict__ b1u,
           const float* __restrict__ W2u, const float* __restrict__ b2u,
           float* __restrict__ out, int N) {
    int g = blockIdx.y;
    const float* x = g ? x2 : x1;
    const float* messages = g_messages + (size_t)g * N * HH;
    const float* att = g_att + (size_t)g * N * DD;
    float* o = out + (size_t)g * N * DD;

    extern __shared__ float sm[];
    float* Ht = sm;
    float* As = Ht + 256 * RP;
    float* Ws = As + 2 * TILE_F;
    unsigned int ws_saddr = (unsigned int)__cvta_generic_to_shared(Ws);

    int tid = threadIdx.x;
    int base = blockIdx.x * 128;
    int ty = tid >> 4, tx = tid & 15;
    int lr = tid >> 1, lk0 = (tid & 1) * 8;
    int wk = tid >> 4, w16 = tid & 15;

    int mynode = base + lr;
    if (mynode >= N) mynode = N - 1;
    const float* rowm = messages + (size_t)mynode * HH;
    const float* rowa = att + (size_t)mynode * DD;
    const float* rowx = x + (size_t)mynode * DD;

    for (int nh = 0; nh < 2; ++nh) {
        unsigned long long c2[8][4];
        #pragma unroll
        for (int i = 0; i < 8; i++)
            #pragma unroll
            for (int j = 0; j < 4; j++) c2[i][j] = 0ull;

        {
            cp_w(ws_saddr, 0, wk, w16, W1u + (size_t)wk * HH + nh * 128);
            cp_commit();
            const float4* p = (const float4*)(rowm + lk0);
            sts_a(As, lk0, lr, p[0], p[1]);
            cp_wait0();
        }
        __syncthreads();

        for (int kt = 0; kt < 32; ++kt) {
            int cur = kt & 1;
            float4 a0, a1;
            bool pf = (kt + 1 < 32);
            if (pf) {
                int kk = (kt + 1) * 16 + lk0;
                const float* src;
                int col;
                if (kk < 256)      { src = rowm; col = kk; }
                else if (kk < 384) { src = rowa; col = kk - 256; }
                else               { src = rowx; col = kk - 384; }
                const float4* p = (const float4*)(src + col);
                a0 = p[0]; a1 = p[1];
                cp_w(ws_saddr, cur ^ 1, wk, w16,
                     W1u + (size_t)((kt + 1) * 16 + wk) * HH + nh * 128);
                cp_commit();
            }
            mma16_f32x2(As + cur * TILE_F, 128, Ws + cur * TILE_F, ty, tx, c2);
            if (pf) sts_a(As + (cur ^ 1) * TILE_F, lk0, lr, a0, a1);
            cp_wait0();
            __syncthreads();
        }

        #pragma unroll
        for (int j = 0; j < 4; ++j) {
            int n0 = nh * 128 + tx * 8 + 2 * j;
            float bj0 = b1u[n0], bj1 = b1u[n0 + 1];
            #pragma unroll
            for (int i = 0; i < 8; ++i) {
                float lo, hi; unpack2(c2[i][j], lo, hi);
                Ht[n0 * RP + ty * 8 + i]       = fmaxf(lo + bj0, 0.f);
                Ht[(n0 + 1) * RP + ty * 8 + i] = fmaxf(hi + bj1, 0.f);
            }
        }
        __syncthreads();
    }

    {
        unsigned long long c2[8][4];
        #pragma unroll
        for (int i = 0; i < 8; i++)
            #pragma unroll
            for (int j = 0; j < 4; j++) c2[i][j] = 0ull;

        cp_w(ws_saddr, 0, wk, w16, W2u + (size_t)wk * DD);
        cp_commit();
        cp_wait0();
        __syncthreads();

        for (int kt = 0; kt < 16; ++kt) {
            int cur = kt & 1;
            bool pf = (kt + 1 < 16);
            if (pf) {
                cp_w(ws_saddr, cur ^ 1, wk, w16, W2u + (size_t)((kt + 1) * 16 + wk) * DD);
                cp_commit();
            }
            mma16_f32x2(Ht + kt * 16 * RP, RP, Ws + cur * TILE_F, ty, tx, c2);
            cp_wait0();
            __syncthreads();
        }

        #pragma unroll
        for (int i = 0; i < 8; i++) {
            int node = base + ty * 8 + i;
            if (node < N) {
                int col = tx * 8;
                float4 r0, r1;
                float lo, hi;
                unpack2(c2[i][0], lo, hi);
                r0.x = lo + b2u[col + 0] + x[(size_t)node * DD + col + 0];
                r0.y = hi + b2u[col + 1] + x[(size_t)node * DD + col + 1];
                unpack2(c2[i][1], lo, hi);
                r0.z = lo + b2u[col + 2] + x[(size_t)node * DD + col + 2];
                r0.w = hi + b2u[col + 3] + x[(size_t)node * DD + col + 3];
                unpack2(c2[i][2], lo, hi);
                r1.x = lo + b2u[col + 4] + x[(size_t)node * DD + col + 4];
                r1.y = hi + b2u[col + 5] + x[(size_t)node * DD + col + 5];
                unpack2(c2[i][3], lo, hi);
                r1.z = lo + b2u[col + 6] + x[(size_t)node * DD + col + 6];
                r1.w = hi + b2u[col + 7] + x[(size_t)node * DD + col + 7];
                *(float4*)(o + (size_t)node * DD + col) = r0;
                *(float4*)(o + (size_t)node * DD + col + 4) = r1;
            }
        }
    }
}

// ---------------- launcher ----------------
extern "C" void kernel_launch(void* const* d_in, const int* in_sizes, int n_in,
                              void* d_out, int out_size) {
    const float* x1   = (const float*)d_in[0];
    const int*   ei1  = (const int*)d_in[1];
    const int*   bat1 = (const int*)d_in[2];
    const float* x2   = (const float*)d_in[3];
    const int*   ei2  = (const int*)d_in[4];
    const int*   bat2 = (const int*)d_in[5];
    const float* mW1 = (const float*)d_in[6];
    const float* mb1 = (const float*)d_in[7];
    const float* mW2 = (const float*)d_in[8];
    const float* mb2 = (const float*)d_in[9];
    const float* uW1 = (const float*)d_in[10];
    const float* ub1 = (const float*)d_in[11];
    const float* uW2 = (const float*)d_in[12];
    const float* ub2 = (const float*)d_in[13];
    float* out = (float*)d_out;

    int N = in_sizes[2];          // nodes per graph
    int E = in_sizes[1] / 2;      // edges per graph

    cudaFuncSetAttribute(msg_mma_kernel, cudaFuncAttributeMaxDynamicSharedMemorySize, MSG_SMEM);
    cudaFuncSetAttribute(upd_kernel, cudaFuncAttributeMaxDynamicSharedMemorySize, UPD_SMEM);

    int zn4 = 2 * N * HH / 4;
    zero_msgs_kernel<<<(zn4 + 255) / 256, 256>>>(zn4);
    seg_kernel<<<1, 128>>>(bat1, bat2, N);
    colmean_kernel<<<2, DD>>>(x1, x2, N);
    prep_w_kernel<<<dim3(256, 2), 256>>>(mW1, mW2);

    dim3 mgrid((E + 63) / 64, 2);
    msg_mma_kernel<<<mgrid, 512, MSG_SMEM>>>(x1, x2, ei1, ei2, mb1, mb2, N, E);

    attn_kernel<<<dim3(NB, 2), 256>>>(x1, x2, N);

    dim3 ugrid((N + 127) / 128, 2);
    upd_kernel<<<ugrid, 256, UPD_SMEM>>>(x1, x2, uW1, ub1, uW2, ub2, out, N);
}

// round 8
// speedup vs baseline: 1.9626x; 1.0499x over previous
#include <cuda_runtime.h>
#include <cuda_bf16.h>
#include <math.h>
#include <stdint.h>

// ---------------- problem constants ----------------
#define DD      128      // node feat dim
#define HH      256      // hidden = 2*D
#define MAXN    8192
#define NB      64       // batches

// scratch (global __device__ arrays: sanctioned, no cudaMalloc)
__device__ float g_messages[2ull * MAXN * HH];   // 16 MB
__device__ float g_att[2ull * MAXN * DD];        // 8 MB
__device__ float g_colmeans[2 * DD];
__device__ int   g_seg[2 * NB * 2];
// pre-split padded bf16 weight tiles (row stride 272 B = 136 bf16)
#define WT_BYTES 69632            // 256 n-rows * 272
#define WT2_BYTES 34816           // 128 n-rows * 272
__device__ __align__(16) unsigned char g_wtile[2][2][2][WT_BYTES];   // msg W1/W2
__device__ __align__(16) unsigned char g_uw1[4][2][WT_BYTES];        // upd W1 (K=512: 4 chunks)
__device__ __align__(16) unsigned char g_uw2[2][2][WT2_BYTES];       // upd W2 (K=256: 2 chunks, 128 n)

// ---------------- PTX helpers ----------------
__device__ __forceinline__ uint32_t smem_u32(const void* p) {
    uint32_t a;
    asm("{ .reg .u64 t; cvta.to.shared.u64 t, %1; cvt.u32.u64 %0, t; }" : "=r"(a) : "l"(p));
    return a;
}
__device__ __forceinline__ void cp_async16(unsigned int saddr, const void* gptr) {
    asm volatile("cp.async.cg.shared.global [%0], [%1], 16;" :: "r"(saddr), "l"(gptr));
}
__device__ __forceinline__ void cp_commit() { asm volatile("cp.async.commit_group;"); }
__device__ __forceinline__ void cp_wait0()  { asm volatile("cp.async.wait_group 0;"); }
__device__ __forceinline__ void red_add_v2(float* p, float a, float b) {
    asm volatile("red.global.add.v2.f32 [%0], {%1,%2};" :: "l"(p), "f"(a), "f"(b) : "memory");
}
__device__ __forceinline__ void ldmx4(uint32_t r[4], uint32_t addr) {
    asm volatile("ldmatrix.sync.aligned.m8n8.x4.shared.b16 {%0,%1,%2,%3}, [%4];"
        : "=r"(r[0]), "=r"(r[1]), "=r"(r[2]), "=r"(r[3]) : "r"(addr));
}
__device__ __forceinline__ void mma_bf16(float d[4], const uint32_t a[4],
                                         uint32_t b0, uint32_t b1) {
    asm volatile("mma.sync.aligned.m16n8k16.row.col.f32.bf16.bf16.f32 "
        "{%0,%1,%2,%3}, {%4,%5,%6,%7}, {%8,%9}, {%0,%1,%2,%3};"
        : "+f"(d[0]), "+f"(d[1]), "+f"(d[2]), "+f"(d[3])
        : "r"(a[0]), "r"(a[1]), "r"(a[2]), "r"(a[3]), "r"(b0), "r"(b1));
}
__device__ __forceinline__ uint32_t pk(__nv_bfloat16 a, __nv_bfloat16 b) {
    __nv_bfloat162 t = __halves2bfloat162(a, b);
    return *reinterpret_cast<uint32_t*>(&t);
}

// ---------------- tiny setup kernels ----------------
__global__ void zero_msgs_kernel(int n4) {
    int i = blockIdx.x * blockDim.x + threadIdx.x;
    if (i < n4) ((float4*)g_messages)[i] = make_float4(0.f, 0.f, 0.f, 0.f);
}

__global__ void seg_kernel(const int* __restrict__ b1, const int* __restrict__ b2, int N) {
    int t = threadIdx.x;
    if (t >= 2 * NB) return;
    int g = t / NB, b = t % NB;
    const int* arr = g ? b2 : b1;
    int lo = 0, hi = N;
    while (lo < hi) { int m = (lo + hi) >> 1; if (arr[m] < b) lo = m + 1; else hi = m; }
    int start = lo;
    lo = 0; hi = N;
    while (lo < hi) { int m = (lo + hi) >> 1; if (arr[m] <= b) lo = m + 1; else hi = m; }
    g_seg[t * 2 + 0] = start;
    g_seg[t * 2 + 1] = lo;
}

__global__ void colmean_kernel(const float* __restrict__ x1, const float* __restrict__ x2, int N) {
    const float* x = blockIdx.x ? x2 : x1;
    int c = threadIdx.x;
    float s0 = 0.f, s1 = 0.f, s2 = 0.f, s3 = 0.f;
    int r = 0;
    for (; r + 3 < N; r += 4) {
        s0 += x[(size_t)(r + 0) * DD + c];
        s1 += x[(size_t)(r + 1) * DD + c];
        s2 += x[(size_t)(r + 2) * DD + c];
        s3 += x[(size_t)(r + 3) * DD + c];
    }
    for (; r < N; ++r) s0 += x[(size_t)r * DD + c];
    g_colmeans[blockIdx.x * DD + c] = (s0 + s1 + s2 + s3) * (1.f / (float)N);
}

__device__ __forceinline__ void split_store(unsigned char* hdst, unsigned char* ldst,
                                            size_t off, float w) {
    __nv_bfloat16 h = __float2bfloat16(w);
    __nv_bfloat16 l = __float2bfloat16(w - __bfloat162float(h));
    *(__nv_bfloat16*)(hdst + off) = h;
    *(__nv_bfloat16*)(ldst + off) = l;
}

// msg weights: W [256k][256n] -> tiles [n][k%128]
__global__ void prep_w_kernel(const float* __restrict__ W1, const float* __restrict__ W2) {
    int layer = blockIdx.y;
    int idx = blockIdx.x * 256 + threadIdx.x;   // k*256 + n
    int k = idx >> 8, n = idx & 255;
    const float* W = layer ? W2 : W1;
    int chunk = k >> 7, kl = k & 127;
    split_store(g_wtile[layer][chunk][0], g_wtile[layer][chunk][1],
                (size_t)n * 272 + (size_t)kl * 2, W[idx]);
}

// upd W1 [512k][256n] -> 4 chunk tiles
__global__ void prep_uw1_kernel(const float* __restrict__ W) {
    int idx = blockIdx.x * 256 + threadIdx.x;   // k*256 + n, 512 blocks
    int k = idx >> 8, n = idx & 255;
    int chunk = k >> 7, kl = k & 127;
    split_store(g_uw1[chunk][0], g_uw1[chunk][1],
                (size_t)n * 272 + (size_t)kl * 2, W[idx]);
}

// upd W2 [256k][128n] -> 2 chunk tiles (128 n-rows)
__global__ void prep_uw2_kernel(const float* __restrict__ W) {
    int idx = blockIdx.x * 256 + threadIdx.x;   // k*128 + n, 128 blocks
    int k = idx >> 7, n = idx & 127;
    int chunk = k >> 7, kl = k & 127;
    split_store(g_uw2[chunk][0], g_uw2[chunk][1],
                (size_t)n * 272 + (size_t)kl * 2, W[idx]);
}

// ---------------- shared mma building blocks ----------------
// SMEM: A_hi [64][136]bf16 (17408B), A_lo, B_hi [256][136]bf16 (69632B), B_lo, ids
#define OFF_AH 0
#define OFF_AL 17408
#define OFF_BH 34816
#define OFF_BL 104448
#define OFF_ID 174080
#define MSG_SMEM (174080 + 1024)

// convert 128 fp32 cols of row `r` (8 threads/row, 16 cols each) into hi/lo A tile
__device__ __forceinline__ void gather_a(char* smc, int r, int seg, const float* __restrict__ rowp) {
    const float4* row = (const float4*)(rowp + seg * 16);
    uint32_t hi[8], lo[8];
    #pragma unroll
    for (int q = 0; q < 4; ++q) {
        float4 v = row[q];
        __nv_bfloat16 h0 = __float2bfloat16(v.x), h1 = __float2bfloat16(v.y);
        __nv_bfloat16 h2 = __float2bfloat16(v.z), h3 = __float2bfloat16(v.w);
        hi[q * 2 + 0] = pk(h0, h1);
        hi[q * 2 + 1] = pk(h2, h3);
        lo[q * 2 + 0] = pk(__float2bfloat16(v.x - __bfloat162float(h0)),
                           __float2bfloat16(v.y - __bfloat162float(h1)));
        lo[q * 2 + 1] = pk(__float2bfloat16(v.z - __bfloat162float(h2)),
                           __float2bfloat16(v.w - __bfloat162float(h3)));
    }
    uint4* dh = (uint4*)(smc + OFF_AH + r * 272 + seg * 32);
    uint4* dl = (uint4*)(smc + OFF_AL + r * 272 + seg * 32);
    dh[0] = make_uint4(hi[0], hi[1], hi[2], hi[3]);
    dh[1] = make_uint4(hi[4], hi[5], hi[6], hi[7]);
    dl[0] = make_uint4(lo[0], lo[1], lo[2], lo[3]);
    dl[1] = make_uint4(lo[4], lo[5], lo[6], lo[7]);
}

// one 128-K mma pass: A [64][128] x B [n_cols][128] -> acc (warp tile 32 x (nt*8))
template<int NT>
__device__ __forceinline__ void mma_pass(uint32_t sb, int wm, int wn, int lane,
                                         float acc[2][NT][4]) {
    #pragma unroll
    for (int ks = 0; ks < 8; ++ks) {
        int k0 = ks * 16;
        uint32_t ah[2][4], al[2][4];
        #pragma unroll
        for (int mt = 0; mt < 2; ++mt) {
            int row = wm * 32 + mt * 16 + (lane & 15);
            uint32_t addr = sb + OFF_AH + row * 272 + (k0 + (lane >> 4) * 8) * 2;
            ldmx4(ah[mt], addr);
            ldmx4(al[mt], addr + (OFF_AL - OFF_AH));
        }
        uint32_t bh[(NT + 1) / 2][4], bl[(NT + 1) / 2][4];
        #pragma unroll
        for (int ntp = 0; ntp < (NT + 1) / 2; ++ntp) {
            int q = lane >> 3, rr = lane & 7;
            int n = wn * (NT * 8) + ntp * 16 + (q >> 1) * 8 + rr;
            int kk = k0 + (q & 1) * 8;
            uint32_t addr = sb + OFF_BH + n * 272 + kk * 2;
            ldmx4(bh[ntp], addr);
            ldmx4(bl[ntp], addr + (OFF_BL - OFF_BH));
        }
        #pragma unroll
        for (int mt = 0; mt < 2; ++mt)
            #pragma unroll
            for (int nt = 0; nt < NT; ++nt) {
                int p = nt >> 1, h2 = (nt & 1) * 2;
                mma_bf16(acc[mt][nt], ah[mt], bh[p][h2], bh[p][h2 + 1]);
                mma_bf16(acc[mt][nt], ah[mt], bl[p][h2], bl[p][h2 + 1]);
                mma_bf16(acc[mt][nt], al[mt], bh[p][h2], bh[p][h2 + 1]);
            }
    }
}

__device__ __forceinline__ void load_b_tile(uint32_t sb, int tid, int nthr,
                                            const unsigned char* hsrc,
                                            const unsigned char* lsrc, int bytes) {
    for (int t = tid; t < bytes / 16; t += nthr) {
        cp_async16(sb + OFF_BH + t * 16, hsrc + t * 16);
        cp_async16(sb + OFF_BL + t * 16, lsrc + t * 16);
    }
    cp_commit();
}

// ---------------- mma.sync message MLP + scatter ----------------
__global__ void __launch_bounds__(512, 1)
msg_mma_kernel(const float* __restrict__ x1, const float* __restrict__ x2,
               const int* __restrict__ ei1, const int* __restrict__ ei2,
               const float* __restrict__ b1, const float* __restrict__ b2,
               int N, int E) {
    int g = blockIdx.y;
    const float* x = g ? x2 : x1;
    const int* ei = g ? ei2 : ei1;
    float* messages = g_messages + (size_t)g * N * HH;

    extern __shared__ char smc[];
    uint32_t sb = smem_u32(smc);
    int* s_src = (int*)(smc + OFF_ID);
    int* s_tgt = s_src + 64;

    int tid = threadIdx.x, wid = tid >> 5, lane = tid & 31;
    int base = blockIdx.x * 64;

    if (tid < 64) {
        int e = base + tid;
        s_tgt[tid] = (e < E) ? ei[e] : 0;
        s_src[tid] = (e < E) ? ei[E + e] : 0;
    }
    __syncthreads();

    int wm = wid & 1;        // row block
    int wn = wid >> 1;       // col block (0..7)
    int gr = lane >> 2, gc = lane & 3;

    float acc[2][4][4];
    #pragma unroll
    for (int mt = 0; mt < 2; ++mt)
        #pragma unroll
        for (int nt = 0; nt < 4; ++nt)
            #pragma unroll
            for (int q = 0; q < 4; ++q) acc[mt][nt][q] = 0.f;

    // layer 1
    for (int c = 0; c < 2; ++c) {
        load_b_tile(sb, tid, 512, g_wtile[0][c][0], g_wtile[0][c][1], WT_BYTES);
        {
            int r = tid >> 3, seg = tid & 7;
            int node = c ? s_tgt[r] : s_src[r];
            gather_a(smc, r, seg, x + (size_t)node * DD);
        }
        cp_wait0();
        __syncthreads();
        mma_pass<4>(sb, wm, wn, lane, acc);
        __syncthreads();
    }

    // bias + relu + split into register fragments
    uint32_t hh[2][4][2], hl[2][4][2];
    #pragma unroll
    for (int nt = 0; nt < 4; ++nt) {
        int col = wn * 32 + nt * 8 + 2 * gc;
        float2 bv = *(const float2*)(b1 + col);
        #pragma unroll
        for (int mt = 0; mt < 2; ++mt) {
            float f0 = fmaxf(acc[mt][nt][0] + bv.x, 0.f);
            float f1 = fmaxf(acc[mt][nt][1] + bv.y, 0.f);
            float f2 = fmaxf(acc[mt][nt][2] + bv.x, 0.f);
            float f3 = fmaxf(acc[mt][nt][3] + bv.y, 0.f);
            __nv_bfloat16 h0 = __float2bfloat16(f0), h1 = __float2bfloat16(f1);
            __nv_bfloat16 h2 = __float2bfloat16(f2), h3 = __float2bfloat16(f3);
            hh[mt][nt][0] = pk(h0, h1);
            hh[mt][nt][1] = pk(h2, h3);
            hl[mt][nt][0] = pk(__float2bfloat16(f0 - __bfloat162float(h0)),
                               __float2bfloat16(f1 - __bfloat162float(h1)));
            hl[mt][nt][1] = pk(__float2bfloat16(f2 - __bfloat162float(h2)),
                               __float2bfloat16(f3 - __bfloat162float(h3)));
            acc[mt][nt][0] = acc[mt][nt][1] = acc[mt][nt][2] = acc[mt][nt][3] = 0.f;
        }
    }

    // layer 2
    for (int c = 0; c < 2; ++c) {
        load_b_tile(sb, tid, 512, g_wtile[1][c][0], g_wtile[1][c][1], WT_BYTES);
        if ((wn >> 2) == c) {
            #pragma unroll
            for (int mt = 0; mt < 2; ++mt) {
                int r = wm * 32 + mt * 16 + gr;
                #pragma unroll
                for (int nt = 0; nt < 4; ++nt) {
                    int cc = (wn & 3) * 32 + nt * 8 + 2 * gc;
                    *(uint32_t*)(smc + OFF_AH + r * 272 + cc * 2)       = hh[mt][nt][0];
                    *(uint32_t*)(smc + OFF_AL + r * 272 + cc * 2)       = hl[mt][nt][0];
                    *(uint32_t*)(smc + OFF_AH + (r + 8) * 272 + cc * 2) = hh[mt][nt][1];
                    *(uint32_t*)(smc + OFF_AL + (r + 8) * 272 + cc * 2) = hl[mt][nt][1];
                }
            }
        }
        cp_wait0();
        __syncthreads();
        mma_pass<4>(sb, wm, wn, lane, acc);
        __syncthreads();
    }

    // scatter-add into messages[tgt]
    #pragma unroll
    for (int mt = 0; mt < 2; ++mt) {
        int r0 = wm * 32 + mt * 16 + gr;
        int r1 = r0 + 8;
        bool v0 = (base + r0) < E, v1 = (base + r1) < E;
        float* m0 = messages + (size_t)s_tgt[r0] * HH;
        float* m1 = messages + (size_t)s_tgt[r1] * HH;
        #pragma unroll
        for (int nt = 0; nt < 4; ++nt) {
            int col = wn * 32 + nt * 8 + 2 * gc;
            float2 bv = *(const float2*)(b2 + col);
            if (v0) red_add_v2(m0 + col, acc[mt][nt][0] + bv.x, acc[mt][nt][1] + bv.y);
            if (v1) red_add_v2(m1 + col, acc[mt][nt][2] + bv.x, acc[mt][nt][3] + bv.y);
        }
    }
}

// ---------------- mma.sync node update MLP ----------------
__global__ void __launch_bounds__(512, 1)
upd_mma_kernel(const float* __restrict__ x1, const float* __restrict__ x2,
               const float* __restrict__ b1u, const float* __restrict__ b2u,
               float* __restrict__ out, int N) {
    int g = blockIdx.y;
    const float* x = g ? x2 : x1;
    const float* messages = g_messages + (size_t)g * N * HH;
    const float* att = g_att + (size_t)g * N * DD;
    float* o = out + (size_t)g * N * DD;

    extern __shared__ char smc[];
    uint32_t sb = smem_u32(smc);

    int tid = threadIdx.x, wid = tid >> 5, lane = tid & 31;
    int base = blockIdx.x * 64;

    int wm = wid & 1;
    int wn = wid >> 1;
    int gr = lane >> 2, gc = lane & 3;

    float acc[2][4][4];
    #pragma unroll
    for (int mt = 0; mt < 2; ++mt)
        #pragma unroll
        for (int nt = 0; nt < 4; ++nt)
            #pragma unroll
            for (int q = 0; q < 4; ++q) acc[mt][nt][q] = 0.f;

    // layer 1: u = [msg(256) | att(128) | x(128)], K = 512 in 4 chunks
    {
        int r = tid >> 3, seg = tid & 7;
        int node = base + r;
        if (node >= N) node = N - 1;
        const float* srcs[4] = {
            messages + (size_t)node * HH,
            messages + (size_t)node * HH + 128,
            att + (size_t)node * DD,
            x + (size_t)node * DD
        };
        for (int c = 0; c < 4; ++c) {
            load_b_tile(sb, tid, 512, g_uw1[c][0], g_uw1[c][1], WT_BYTES);
            gather_a(smc, r, seg, srcs[c]);
            cp_wait0();
            __syncthreads();
            mma_pass<4>(sb, wm, wn, lane, acc);
            __syncthreads();
        }
    }

    // bias + relu + split
    uint32_t hh[2][4][2], hl[2][4][2];
    #pragma unroll
    for (int nt = 0; nt < 4; ++nt) {
        int col = wn * 32 + nt * 8 + 2 * gc;
        float2 bv = *(const float2*)(b1u + col);
        #pragma unroll
        for (int mt = 0; mt < 2; ++mt) {
            float f0 = fmaxf(acc[mt][nt][0] + bv.x, 0.f);
            float f1 = fmaxf(acc[mt][nt][1] + bv.y, 0.f);
            float f2 = fmaxf(acc[mt][nt][2] + bv.x, 0.f);
            float f3 = fmaxf(acc[mt][nt][3] + bv.y, 0.f);
            __nv_bfloat16 h0 = __float2bfloat16(f0), h1 = __float2bfloat16(f1);
            __nv_bfloat16 h2 = __float2bfloat16(f2), h3 = __float2bfloat16(f3);
            hh[mt][nt][0] = pk(h0, h1);
            hh[mt][nt][1] = pk(h2, h3);
            hl[mt][nt][0] = pk(__float2bfloat16(f0 - __bfloat162float(h0)),
                               __float2bfloat16(f1 - __bfloat162float(h1)));
            hl[mt][nt][1] = pk(__float2bfloat16(f2 - __bfloat162float(h2)),
                               __float2bfloat16(f3 - __bfloat162float(h3)));
            acc[mt][nt][0] = acc[mt][nt][1] = acc[mt][nt][2] = acc[mt][nt][3] = 0.f;
        }
    }

    // layer 2: N=128 out, K=256 in 2 chunks; warp tile 32 x 16 (wn2 = wid>>1)
    int wm2 = wid & 1, wn2 = wid >> 1;
    for (int c = 0; c < 2; ++c) {
        load_b_tile(sb, tid, 512, g_uw2[c][0], g_uw2[c][1], WT2_BYTES);
        if ((wn >> 2) == c) {
            #pragma unroll
            for (int mt = 0; mt < 2; ++mt) {
                int r = wm * 32 + mt * 16 + gr;
                #pragma unroll
                for (int nt = 0; nt < 4; ++nt) {
                    int cc = (wn & 3) * 32 + nt * 8 + 2 * gc;
                    *(uint32_t*)(smc + OFF_AH + r * 272 + cc * 2)       = hh[mt][nt][0];
                    *(uint32_t*)(smc + OFF_AL + r * 272 + cc * 2)       = hl[mt][nt][0];
                    *(uint32_t*)(smc + OFF_AH + (r + 8) * 272 + cc * 2) = hh[mt][nt][1];
                    *(uint32_t*)(smc + OFF_AL + (r + 8) * 272 + cc * 2) = hl[mt][nt][1];
                }
            }
        }
        cp_wait0();
        __syncthreads();
        mma_pass<2>(sb, wm2, wn2, lane, (float (*)[2][4])acc);
        __syncthreads();
    }

    // epilogue: out = x + D + b2u
    float (*acc2)[2][4] = (float (*)[2][4])acc;
    #pragma unroll
    for (int mt = 0; mt < 2; ++mt) {
        int r0 = wm2 * 32 + mt * 16 + gr;
        int r1 = r0 + 8;
        int n0 = base + r0, n1 = base + r1;
        #pragma unroll
        for (int nt = 0; nt < 2; ++nt) {
            int col = wn2 * 16 + nt * 8 + 2 * gc;
            float2 bv = *(const float2*)(b2u + col);
            if (n0 < N) {
                float2 xv = *(const float2*)(x + (size_t)n0 * DD + col);
                float2 r;
                r.x = acc2[mt][nt][0] + bv.x + xv.x;
                r.y = acc2[mt][nt][1] + bv.y + xv.y;
                *(float2*)(o + (size_t)n0 * DD + col) = r;
            }
            if (n1 < N) {
                float2 xv = *(const float2*)(x + (size_t)n1 * DD + col);
                float2 r;
                r.x = acc2[mt][nt][2] + bv.x + xv.x;
                r.y = acc2[mt][nt][3] + bv.y + xv.y;
                *(float2*)(o + (size_t)n1 * DD + col) = r;
            }
        }
    }
}

// ---------------- block-diagonal cross attention (unchanged) ----------------
__global__ void attn_kernel(const float* __restrict__ x1,
                            const float* __restrict__ x2, int N) {
    int b = blockIdx.x;
    int dir = blockIdx.y;
    const float* rowsrc = dir ? x2 : x1;
    const float* colsrc = dir ? x1 : x2;
    float* att = g_att + (size_t)dir * N * DD;
    int rs = g_seg[(dir * NB + b) * 2 + 0];
    int re = g_seg[(dir * NB + b) * 2 + 1];
    int cs = g_seg[((1 - dir) * NB + b) * 2 + 0];
    int ce = g_seg[((1 - dir) * NB + b) * 2 + 1];
    const float* mean = g_colmeans + (1 - dir) * DD;

    int warp = threadIdx.x >> 5, lane = threadIdx.x & 31;

    for (int i = rs + warp; i < re; i += 8) {
        float4 a = *(const float4*)(rowsrc + (size_t)i * DD + lane * 4);
        float4 res;
        if (cs == ce) {
            float4 mv = *(const float4*)(mean + lane * 4);
            res.x = a.x - mv.x; res.y = a.y - mv.y;
            res.z = a.z - mv.z; res.w = a.w - mv.w;
        } else {
            float m = -3.4e38f;
            for (int j = cs; j < ce; ++j) {
                float4 bv = *(const float4*)(colsrc + (size_t)j * DD + lane * 4);
                float d = a.x * bv.x + a.y * bv.y + a.z * bv.z + a.w * bv.w;
                #pragma unroll
                for (int o = 16; o; o >>= 1) d += __shfl_xor_sync(0xffffffffu, d, o);
                m = fmaxf(m, d);
            }
            float se = 0.f;
            float4 acc = make_float4(0.f, 0.f, 0.f, 0.f);
            for (int j = cs; j < ce; ++j) {
                float4 bv = *(const float4*)(colsrc + (size_t)j * DD + lane * 4);
                float d = a.x * bv.x + a.y * bv.y + a.z * bv.z + a.w * bv.w;
                #pragma unroll
                for (int o = 16; o; o >>= 1) d += __shfl_xor_sync(0xffffffffu, d, o);
                float w = __expf(d - m);
                se += w;
                acc.x = fmaf(w, bv.x, acc.x);
                acc.y = fmaf(w, bv.y, acc.y);
                acc.z = fmaf(w, bv.z, acc.z);
                acc.w = fmaf(w, bv.w, acc.w);
            }
            float inv = 1.f / se;
            res.x = a.x - acc.x * inv; res.y = a.y - acc.y * inv;
            res.z = a.z - acc.z * inv; res.w = a.w - acc.w * inv;
        }
        *(float4*)(att + (size_t)i * DD + lane * 4) = res;
    }
}

// ---------------- launcher ----------------
extern "C" void kernel_launch(void* const* d_in, const int* in_sizes, int n_in,
                              void* d_out, int out_size) {
    const float* x1   = (const float*)d_in[0];
    const int*   ei1  = (const int*)d_in[1];
    const int*   bat1 = (const int*)d_in[2];
    const float* x2   = (const float*)d_in[3];
    const int*   ei2  = (const int*)d_in[4];
    const int*   bat2 = (const int*)d_in[5];
    const float* mW1 = (const float*)d_in[6];
    const float* mb1 = (const float*)d_in[7];
    const float* mW2 = (const float*)d_in[8];
    const float* mb2 = (const float*)d_in[9];
    const float* uW1 = (const float*)d_in[10];
    const float* ub1 = (const float*)d_in[11];
    const float* uW2 = (const float*)d_in[12];
    const float* ub2 = (const float*)d_in[13];
    float* out = (float*)d_out;

    int N = in_sizes[2];          // nodes per graph
    int E = in_sizes[1] / 2;      // edges per graph

    cudaFuncSetAttribute(msg_mma_kernel, cudaFuncAttributeMaxDynamicSharedMemorySize, MSG_SMEM);
    cudaFuncSetAttribute(upd_mma_kernel, cudaFuncAttributeMaxDynamicSharedMemorySize, MSG_SMEM);

    int zn4 = 2 * N * HH / 4;
    zero_msgs_kernel<<<(zn4 + 255) / 256, 256>>>(zn4);
    seg_kernel<<<1, 128>>>(bat1, bat2, N);
    colmean_kernel<<<2, DD>>>(x1, x2, N);
    prep_w_kernel<<<dim3(256, 2), 256>>>(mW1, mW2);
    prep_uw1_kernel<<<512, 256>>>(uW1);
    prep_uw2_kernel<<<128, 256>>>(uW2);

    dim3 mgrid((E + 63) / 64, 2);
    msg_mma_kernel<<<mgrid, 512, MSG_SMEM>>>(x1, x2, ei1, ei2, mb1, mb2, N, E);

    attn_kernel<<<dim3(NB, 2), 256>>>(x1, x2, N);

    dim3 ugrid((N + 63) / 64, 2);
    upd_mma_kernel<<<ugrid, 512, MSG_SMEM>>>(x1, x2, ub1, ub2, out, N);
}

// round 9
// speedup vs baseline: 1.9741x; 1.0059x over previous
#include <cuda_runtime.h>
#include <cuda_bf16.h>
#include <math.h>
#include <stdint.h>

// ---------------- problem constants ----------------
#define DD      128
#define HH      256
#define MAXN    8192
#define NB      64
#define NTHR    512

// scratch
__device__ float g_messages[2ull * MAXN * HH];
__device__ float g_att[2ull * MAXN * DD];
__device__ float g_colmeans[2 * DD];
__device__ int   g_seg[2 * NB * 2];
// K=64-sliced padded bf16 weight tiles, row stride 144 B (64 data cols + 8 pad)
#define HCT_BYTES  36864    // 256 n-rows * 144
#define HCT2_BYTES 18432    // 128 n-rows * 144
__device__ __align__(16) unsigned char g_wtile[2][4][2][HCT_BYTES]; // msg W1/W2
__device__ __align__(16) unsigned char g_uw1[8][2][HCT_BYTES];      // upd W1 (K=512)
__device__ __align__(16) unsigned char g_uw2[4][2][HCT2_BYTES];     // upd W2 (K=256, N=128)

// ---------------- PTX helpers ----------------
__device__ __forceinline__ uint32_t smem_u32(const void* p) {
    uint32_t a;
    asm("{ .reg .u64 t; cvta.to.shared.u64 t, %1; cvt.u32.u64 %0, t; }" : "=r"(a) : "l"(p));
    return a;
}
__device__ __forceinline__ void cp_async16(unsigned int saddr, const void* gptr) {
    asm volatile("cp.async.cg.shared.global [%0], [%1], 16;" :: "r"(saddr), "l"(gptr));
}
__device__ __forceinline__ void cp_commit() { asm volatile("cp.async.commit_group;"); }
template<int N>
__device__ __forceinline__ void cp_wait() { asm volatile("cp.async.wait_group %0;" :: "n"(N)); }
__device__ __forceinline__ void red_add_v2(float* p, float a, float b) {
    asm volatile("red.global.add.v2.f32 [%0], {%1,%2};" :: "l"(p), "f"(a), "f"(b) : "memory");
}
__device__ __forceinline__ void ldmx4(uint32_t r[4], uint32_t addr) {
    asm volatile("ldmatrix.sync.aligned.m8n8.x4.shared.b16 {%0,%1,%2,%3}, [%4];"
        : "=r"(r[0]), "=r"(r[1]), "=r"(r[2]), "=r"(r[3]) : "r"(addr));
}
__device__ __forceinline__ void mma_bf16(float d[4], const uint32_t a[4],
                                         uint32_t b0, uint32_t b1) {
    asm volatile("mma.sync.aligned.m16n8k16.row.col.f32.bf16.bf16.f32 "
        "{%0,%1,%2,%3}, {%4,%5,%6,%7}, {%8,%9}, {%0,%1,%2,%3};"
        : "+f"(d[0]), "+f"(d[1]), "+f"(d[2]), "+f"(d[3])
        : "r"(a[0]), "r"(a[1]), "r"(a[2]), "r"(a[3]), "r"(b0), "r"(b1));
}
__device__ __forceinline__ uint32_t pk(__nv_bfloat16 a, __nv_bfloat16 b) {
    __nv_bfloat162 t = __halves2bfloat162(a, b);
    return *reinterpret_cast<uint32_t*>(&t);
}

// ---------------- tiny setup kernels ----------------
__global__ void zero_msgs_kernel(int n4) {
    int i = blockIdx.x * blockDim.x + threadIdx.x;
    if (i < n4) ((float4*)g_messages)[i] = make_float4(0.f, 0.f, 0.f, 0.f);
}

__global__ void seg_kernel(const int* __restrict__ b1, const int* __restrict__ b2, int N) {
    int t = threadIdx.x;
    if (t >= 2 * NB) return;
    int g = t / NB, b = t % NB;
    const int* arr = g ? b2 : b1;
    int lo = 0, hi = N;
    while (lo < hi) { int m = (lo + hi) >> 1; if (arr[m] < b) lo = m + 1; else hi = m; }
    int start = lo;
    lo = 0; hi = N;
    while (lo < hi) { int m = (lo + hi) >> 1; if (arr[m] <= b) lo = m + 1; else hi = m; }
    g_seg[t * 2 + 0] = start;
    g_seg[t * 2 + 1] = lo;
}

__global__ void colmean_kernel(const float* __restrict__ x1, const float* __restrict__ x2, int N) {
    const float* x = blockIdx.x ? x2 : x1;
    int c = threadIdx.x;
    float s0 = 0.f, s1 = 0.f, s2 = 0.f, s3 = 0.f;
    int r = 0;
    for (; r + 3 < N; r += 4) {
        s0 += x[(size_t)(r + 0) * DD + c];
        s1 += x[(size_t)(r + 1) * DD + c];
        s2 += x[(size_t)(r + 2) * DD + c];
        s3 += x[(size_t)(r + 3) * DD + c];
    }
    for (; r < N; ++r) s0 += x[(size_t)r * DD + c];
    g_colmeans[blockIdx.x * DD + c] = (s0 + s1 + s2 + s3) * (1.f / (float)N);
}

__device__ __forceinline__ void split_store(unsigned char* hdst, unsigned char* ldst,
                                            size_t off, float w) {
    __nv_bfloat16 h = __float2bfloat16(w);
    __nv_bfloat16 l = __float2bfloat16(w - __bfloat162float(h));
    *(__nv_bfloat16*)(hdst + off) = h;
    *(__nv_bfloat16*)(ldst + off) = l;
}

// merged weight prep: msg W1/W2 (65536 each), upd W1 (131072), upd W2 (32768)
__global__ void prep_all_kernel(const float* __restrict__ mW1, const float* __restrict__ mW2,
                                const float* __restrict__ uW1, const float* __restrict__ uW2) {
    int idx = blockIdx.x * 256 + threadIdx.x;
    if (idx < 131072) {
        int layer = idx >> 16;
        int e = idx & 65535;
        int k = e >> 8, n = e & 255;
        const float* W = layer ? mW2 : mW1;
        split_store(g_wtile[layer][k >> 6][0], g_wtile[layer][k >> 6][1],
                    (size_t)n * 144 + (size_t)(k & 63) * 2, W[e]);
    } else if (idx < 262144) {
        int e = idx - 131072;
        int k = e >> 8, n = e & 255;
        split_store(g_uw1[k >> 6][0], g_uw1[k >> 6][1],
                    (size_t)n * 144 + (size_t)(k & 63) * 2, uW1[e]);
    } else {
        int e = idx - 262144;
        int k = e >> 7, n = e & 127;
        split_store(g_uw2[k >> 6][0], g_uw2[k >> 6][1],
                    (size_t)n * 144 + (size_t)(k & 63) * 2, uW2[e]);
    }
}

// ---------------- shared mma building blocks ----------------
// SMEM: A_hi [64][136]bf16, A_lo, B double buffer (each: BH 36864 + BL 36864), ids
#define OFF_AH 0
#define OFF_AL 17408
#define OFF_B  34816
#define BBUF_BYTES 73728
#define OFF_ID (34816 + 2*BBUF_BYTES)       // 182272
#define MSG_SMEM (OFF_ID + 1024)

// convert 128 fp32 cols of row r (8 threads/row, 16 cols each) into hi/lo A tile
__device__ __forceinline__ void gather_a(char* smc, int r, int seg, const float* __restrict__ rowp) {
    const float4* row = (const float4*)(rowp + seg * 16);
    uint32_t hi[8], lo[8];
    #pragma unroll
    for (int q = 0; q < 4; ++q) {
        float4 v = row[q];
        __nv_bfloat16 h0 = __float2bfloat16(v.x), h1 = __float2bfloat16(v.y);
        __nv_bfloat16 h2 = __float2bfloat16(v.z), h3 = __float2bfloat16(v.w);
        hi[q * 2 + 0] = pk(h0, h1);
        hi[q * 2 + 1] = pk(h2, h3);
        lo[q * 2 + 0] = pk(__float2bfloat16(v.x - __bfloat162float(h0)),
                           __float2bfloat16(v.y - __bfloat162float(h1)));
        lo[q * 2 + 1] = pk(__float2bfloat16(v.z - __bfloat162float(h2)),
                           __float2bfloat16(v.w - __bfloat162float(h3)));
    }
    uint4* dh = (uint4*)(smc + OFF_AH + r * 272 + seg * 32);
    uint4* dl = (uint4*)(smc + OFF_AL + r * 272 + seg * 32);
    dh[0] = make_uint4(hi[0], hi[1], hi[2], hi[3]);
    dh[1] = make_uint4(hi[4], hi[5], hi[6], hi[7]);
    dl[0] = make_uint4(lo[0], lo[1], lo[2], lo[3]);
    dl[1] = make_uint4(lo[4], lo[5], lo[6], lo[7]);
}

// one half-chunk (K=64) mma pass
template<int NT>
__device__ __forceinline__ void mma_hc(uint32_t sb, int a_k0, uint32_t b_base,
                                       int wm, int wn, int lane, float acc[2][NT][4]) {
    #pragma unroll
    for (int ks = 0; ks < 4; ++ks) {
        int k0 = ks * 16;
        uint32_t ah[2][4], al[2][4];
        #pragma unroll
        for (int mt = 0; mt < 2; ++mt) {
            int row = wm * 32 + mt * 16 + (lane & 15);
            uint32_t addr = sb + OFF_AH + row * 272 + (a_k0 + k0 + (lane >> 4) * 8) * 2;
            ldmx4(ah[mt], addr);
            ldmx4(al[mt], addr + (OFF_AL - OFF_AH));
        }
        uint32_t bh[(NT + 1) / 2][4], bl[(NT + 1) / 2][4];
        #pragma unroll
        for (int ntp = 0; ntp < (NT + 1) / 2; ++ntp) {
            int q = lane >> 3, rr = lane & 7;
            int n = wn * (NT * 8) + ntp * 16 + (q >> 1) * 8 + rr;
            int kk = k0 + (q & 1) * 8;
            uint32_t addr = b_base + n * 144 + kk * 2;
            ldmx4(bh[ntp], addr);
            ldmx4(bl[ntp], addr + HCT_BYTES);
        }
        #pragma unroll
        for (int mt = 0; mt < 2; ++mt)
            #pragma unroll
            for (int nt = 0; nt < NT; ++nt) {
                int p = nt >> 1, h2 = (nt & 1) * 2;
                mma_bf16(acc[mt][nt], ah[mt], bh[p][h2], bh[p][h2 + 1]);
                mma_bf16(acc[mt][nt], ah[mt], bl[p][h2], bl[p][h2 + 1]);
                mma_bf16(acc[mt][nt], al[mt], bh[p][h2], bh[p][h2 + 1]);
            }
    }
}

__device__ __forceinline__ void load_b_hc(uint32_t b_base, int tid,
                                          const unsigned char* hsrc,
                                          const unsigned char* lsrc, int lines) {
    for (int t = tid; t < lines; t += NTHR) {
        cp_async16(b_base + t * 16, hsrc + t * 16);
        cp_async16(b_base + HCT_BYTES + t * 16, lsrc + t * 16);
    }
    cp_commit();
}

// ---------------- mma.sync message MLP + scatter ----------------
__global__ void __launch_bounds__(NTHR, 1)
msg_mma_kernel(const float* __restrict__ x1, const float* __restrict__ x2,
               const int* __restrict__ ei1, const int* __restrict__ ei2,
               const float* __restrict__ b1, const float* __restrict__ b2,
               int N, int E) {
    int g = blockIdx.y;
    const float* x = g ? x2 : x1;
    const int* ei = g ? ei2 : ei1;
    float* messages = g_messages + (size_t)g * N * HH;

    extern __shared__ char smc[];
    uint32_t sb = smem_u32(smc);
    int* s_src = (int*)(smc + OFF_ID);
    int* s_tgt = s_src + 64;

    int tid = threadIdx.x, wid = tid >> 5, lane = tid & 31;
    int base = blockIdx.x * 64;

    if (tid < 64) {
        int e = base + tid;
        s_tgt[tid] = (e < E) ? ei[e] : 0;
        s_src[tid] = (e < E) ? ei[E + e] : 0;
    }
    __syncthreads();

    int wm = wid & 1, wn = wid >> 1;
    int gr = lane >> 2, gc = lane & 3;
    int r = tid >> 3, seg = tid & 7;
    uint32_t bbuf[2] = { sb + OFF_B, sb + OFF_B + BBUF_BYTES };

    float acc[2][4][4];
    #pragma unroll
    for (int mt = 0; mt < 2; ++mt)
        #pragma unroll
        for (int nt = 0; nt < 4; ++nt)
            #pragma unroll
            for (int q = 0; q < 4; ++q) acc[mt][nt][q] = 0.f;

    // -------- layer 1 (K=256: 4 half-chunks; A blocks: x_src, x_tgt) --------
    load_b_hc(bbuf[0], tid, g_wtile[0][0][0], g_wtile[0][0][1], 2304);
    gather_a(smc, r, seg, x + (size_t)s_src[r] * DD);
    load_b_hc(bbuf[1], tid, g_wtile[0][1][0], g_wtile[0][1][1], 2304);
    cp_wait<1>();
    __syncthreads();

    #pragma unroll
    for (int hc = 0; hc < 4; ++hc) {
        mma_hc<4>(sb, (hc & 1) * 64, bbuf[hc & 1], wm, wn, lane, acc);
        __syncthreads();
        if (hc == 1) gather_a(smc, r, seg, x + (size_t)s_tgt[r] * DD);
        if (hc + 2 < 4) {
            load_b_hc(bbuf[hc & 1], tid, g_wtile[0][hc + 2][0], g_wtile[0][hc + 2][1], 2304);
            cp_wait<1>();
        } else if (hc + 1 < 4) {
            cp_wait<0>();
        }
        __syncthreads();
    }

    // bias + relu + split into register fragments
    uint32_t hh[2][4][2], hl[2][4][2];
    #pragma unroll
    for (int nt = 0; nt < 4; ++nt) {
        int col = wn * 32 + nt * 8 + 2 * gc;
        float2 bv = *(const float2*)(b1 + col);
        #pragma unroll
        for (int mt = 0; mt < 2; ++mt) {
            float f0 = fmaxf(acc[mt][nt][0] + bv.x, 0.f);
            float f1 = fmaxf(acc[mt][nt][1] + bv.y, 0.f);
            float f2 = fmaxf(acc[mt][nt][2] + bv.x, 0.f);
            float f3 = fmaxf(acc[mt][nt][3] + bv.y, 0.f);
            __nv_bfloat16 h0 = __float2bfloat16(f0), h1 = __float2bfloat16(f1);
            __nv_bfloat16 h2 = __float2bfloat16(f2), h3 = __float2bfloat16(f3);
            hh[mt][nt][0] = pk(h0, h1);
            hh[mt][nt][1] = pk(h2, h3);
            hl[mt][nt][0] = pk(__float2bfloat16(f0 - __bfloat162float(h0)),
                               __float2bfloat16(f1 - __bfloat162float(h1)));
            hl[mt][nt][1] = pk(__float2bfloat16(f2 - __bfloat162float(h2)),
                               __float2bfloat16(f3 - __bfloat162float(h3)));
            acc[mt][nt][0] = acc[mt][nt][1] = acc[mt][nt][2] = acc[mt][nt][3] = 0.f;
        }
    }

    // -------- layer 2 (K=256: 4 half-chunks; A blocks = H fragments) --------
    load_b_hc(bbuf[0], tid, g_wtile[1][0][0], g_wtile[1][0][1], 2304);
    if (wn < 4) {
        #pragma unroll
        for (int mt = 0; mt < 2; ++mt) {
            int rr = wm * 32 + mt * 16 + gr;
            #pragma unroll
            for (int nt = 0; nt < 4; ++nt) {
                int cc = wn * 32 + nt * 8 + 2 * gc;
                *(uint32_t*)(smc + OFF_AH + rr * 272 + cc * 2)       = hh[mt][nt][0];
                *(uint32_t*)(smc + OFF_AL + rr * 272 + cc * 2)       = hl[mt][nt][0];
                *(uint32_t*)(smc + OFF_AH + (rr + 8) * 272 + cc * 2) = hh[mt][nt][1];
                *(uint32_t*)(smc + OFF_AL + (rr + 8) * 272 + cc * 2) = hl[mt][nt][1];
            }
        }
    }
    load_b_hc(bbuf[1], tid, g_wtile[1][1][0], g_wtile[1][1][1], 2304);
    cp_wait<1>();
    __syncthreads();

    #pragma unroll
    for (int hc = 0; hc < 4; ++hc) {
        mma_hc<4>(sb, (hc & 1) * 64, bbuf[hc & 1], wm, wn, lane, acc);
        __syncthreads();
        if (hc == 1 && wn >= 4) {
            #pragma unroll
            for (int mt = 0; mt < 2; ++mt) {
                int rr = wm * 32 + mt * 16 + gr;
                #pragma unroll
                for (int nt = 0; nt < 4; ++nt) {
                    int cc = (wn & 3) * 32 + nt * 8 + 2 * gc;
                    *(uint32_t*)(smc + OFF_AH + rr * 272 + cc * 2)       = hh[mt][nt][0];
                    *(uint32_t*)(smc + OFF_AL + rr * 272 + cc * 2)       = hl[mt][nt][0];
                    *(uint32_t*)(smc + OFF_AH + (rr + 8) * 272 + cc * 2) = hh[mt][nt][1];
                    *(uint32_t*)(smc + OFF_AL + (rr + 8) * 272 + cc * 2) = hl[mt][nt][1];
                }
            }
        }
        if (hc + 2 < 4) {
            load_b_hc(bbuf[hc & 1], tid, g_wtile[1][hc + 2][0], g_wtile[1][hc + 2][1], 2304);
            cp_wait<1>();
        } else if (hc + 1 < 4) {
            cp_wait<0>();
        }
        __syncthreads();
    }

    // scatter-add into messages[tgt]
    #pragma unroll
    for (int mt = 0; mt < 2; ++mt) {
        int r0 = wm * 32 + mt * 16 + gr;
        int r1 = r0 + 8;
        bool v0 = (base + r0) < E, v1 = (base + r1) < E;
        float* m0 = messages + (size_t)s_tgt[r0] * HH;
        float* m1 = messages + (size_t)s_tgt[r1] * HH;
        #pragma unroll
        for (int nt = 0; nt < 4; ++nt) {
            int col = wn * 32 + nt * 8 + 2 * gc;
            float2 bv = *(const float2*)(b2 + col);
            if (v0) red_add_v2(m0 + col, acc[mt][nt][0] + bv.x, acc[mt][nt][1] + bv.y);
            if (v1) red_add_v2(m1 + col, acc[mt][nt][2] + bv.x, acc[mt][nt][3] + bv.y);
        }
    }
}

// ---------------- mma.sync node update MLP ----------------
__global__ void __launch_bounds__(NTHR, 1)
upd_mma_kernel(const float* __restrict__ x1, const float* __restrict__ x2,
               const float* __restrict__ b1u, const float* __restrict__ b2u,
               float* __restrict__ out, int N) {
    int g = blockIdx.y;
    const float* x = g ? x2 : x1;
    const float* messages = g_messages + (size_t)g * N * HH;
    const float* att = g_att + (size_t)g * N * DD;
    float* o = out + (size_t)g * N * DD;

    extern __shared__ char smc[];
    uint32_t sb = smem_u32(smc);

    int tid = threadIdx.x, wid = tid >> 5, lane = tid & 31;
    int base = blockIdx.x * 64;
    int wm = wid & 1, wn = wid >> 1;
    int gr = lane >> 2, gc = lane & 3;
    int r = tid >> 3, seg = tid & 7;
    uint32_t bbuf[2] = { sb + OFF_B, sb + OFF_B + BBUF_BYTES };

    int node = base + r;
    if (node >= N) node = N - 1;
    const float* srcs[4] = {
        messages + (size_t)node * HH,
        messages + (size_t)node * HH + 128,
        att + (size_t)node * DD,
        x + (size_t)node * DD
    };

    float acc[2][4][4];
    #pragma unroll
    for (int mt = 0; mt < 2; ++mt)
        #pragma unroll
        for (int nt = 0; nt < 4; ++nt)
            #pragma unroll
            for (int q = 0; q < 4; ++q) acc[mt][nt][q] = 0.f;

    // -------- layer 1 (K=512: 8 half-chunks; 4 A blocks) --------
    load_b_hc(bbuf[0], tid, g_uw1[0][0], g_uw1[0][1], 2304);
    gather_a(smc, r, seg, srcs[0]);
    load_b_hc(bbuf[1], tid, g_uw1[1][0], g_uw1[1][1], 2304);
    cp_wait<1>();
    __syncthreads();

    #pragma unroll
    for (int hc = 0; hc < 8; ++hc) {
        mma_hc<4>(sb, (hc & 1) * 64, bbuf[hc & 1], wm, wn, lane, acc);
        __syncthreads();
        if ((hc & 1) == 1 && hc < 7) gather_a(smc, r, seg, srcs[(hc + 1) >> 1]);
        if (hc + 2 < 8) {
            load_b_hc(bbuf[hc & 1], tid, g_uw1[hc + 2][0], g_uw1[hc + 2][1], 2304);
            cp_wait<1>();
        } else if (hc + 1 < 8) {
            cp_wait<0>();
        }
        __syncthreads();
    }

    // bias + relu + split
    uint32_t hh[2][4][2], hl[2][4][2];
    #pragma unroll
    for (int nt = 0; nt < 4; ++nt) {
        int col = wn * 32 + nt * 8 + 2 * gc;
        float2 bv = *(const float2*)(b1u + col);
        #pragma unroll
        for (int mt = 0; mt < 2; ++mt) {
            float f0 = fmaxf(acc[mt][nt][0] + bv.x, 0.f);
            float f1 = fmaxf(acc[mt][nt][1] + bv.y, 0.f);
            float f2 = fmaxf(acc[mt][nt][2] + bv.x, 0.f);
            float f3 = fmaxf(acc[mt][nt][3] + bv.y, 0.f);
            __nv_bfloat16 h0 = __float2bfloat16(f0), h1 = __float2bfloat16(f1);
            __nv_bfloat16 h2 = __float2bfloat16(f2), h3 = __float2bfloat16(f3);
            hh[mt][nt][0] = pk(h0, h1);
            hh[mt][nt][1] = pk(h2, h3);
            hl[mt][nt][0] = pk(__float2bfloat16(f0 - __bfloat162float(h0)),
                               __float2bfloat16(f1 - __bfloat162float(h1)));
            hl[mt][nt][1] = pk(__float2bfloat16(f2 - __bfloat162float(h2)),
                               __float2bfloat16(f3 - __bfloat162float(h3)));
            acc[mt][nt][0] = acc[mt][nt][1] = acc[mt][nt][2] = acc[mt][nt][3] = 0.f;
        }
    }

    // -------- layer 2 (K=256: 4 half-chunks; N=128, warp tile 32x16) --------
    int wm2 = wid & 1, wn2 = wid >> 1;
    float (*acc2)[2][4] = (float (*)[2][4])acc;

    load_b_hc(bbuf[0], tid, g_uw2[0][0], g_uw2[0][1], 1152);
    if (wn < 4) {
        #pragma unroll
        for (int mt = 0; mt < 2; ++mt) {
            int rr = wm * 32 + mt * 16 + gr;
            #pragma unroll
            for (int nt = 0; nt < 4; ++nt) {
                int cc = wn * 32 + nt * 8 + 2 * gc;
                *(uint32_t*)(smc + OFF_AH + rr * 272 + cc * 2)       = hh[mt][nt][0];
                *(uint32_t*)(smc + OFF_AL + rr * 272 + cc * 2)       = hl[mt][nt][0];
                *(uint32_t*)(smc + OFF_AH + (rr + 8) * 272 + cc * 2) = hh[mt][nt][1];
                *(uint32_t*)(smc + OFF_AL + (rr + 8) * 272 + cc * 2) = hl[mt][nt][1];
            }
        }
    }
    load_b_hc(bbuf[1], tid, g_uw2[1][0], g_uw2[1][1], 1152);
    cp_wait<1>();
    __syncthreads();

    #pragma unroll
    for (int hc = 0; hc < 4; ++hc) {
        mma_hc<2>(sb, (hc & 1) * 64, bbuf[hc & 1], wm2, wn2, lane, acc2);
        __syncthreads();
        if (hc == 1 && wn >= 4) {
            #pragma unroll
            for (int mt = 0; mt < 2; ++mt) {
                int rr = wm * 32 + mt * 16 + gr;
                #pragma unroll
                for (int nt = 0; nt < 4; ++nt) {
                    int cc = (wn & 3) * 32 + nt * 8 + 2 * gc;
                    *(uint32_t*)(smc + OFF_AH + rr * 272 + cc * 2)       = hh[mt][nt][0];
                    *(uint32_t*)(smc + OFF_AL + rr * 272 + cc * 2)       = hl[mt][nt][0];
                    *(uint32_t*)(smc + OFF_AH + (rr + 8) * 272 + cc * 2) = hh[mt][nt][1];
                    *(uint32_t*)(smc + OFF_AL + (rr + 8) * 272 + cc * 2) = hl[mt][nt][1];
                }
            }
        }
        if (hc + 2 < 4) {
            load_b_hc(bbuf[hc & 1], tid, g_uw2[hc + 2][0], g_uw2[hc + 2][1], 1152);
            cp_wait<1>();
        } else if (hc + 1 < 4) {
            cp_wait<0>();
        }
        __syncthreads();
    }

    // epilogue: out = x + D + b2u
    #pragma unroll
    for (int mt = 0; mt < 2; ++mt) {
        int r0 = wm2 * 32 + mt * 16 + gr;
        int r1 = r0 + 8;
        int n0 = base + r0, n1 = base + r1;
        #pragma unroll
        for (int nt = 0; nt < 2; ++nt) {
            int col = wn2 * 16 + nt * 8 + 2 * gc;
            float2 bv = *(const float2*)(b2u + col);
            if (n0 < N) {
                float2 xv = *(const float2*)(x + (size_t)n0 * DD + col);
                float2 rr;
                rr.x = acc2[mt][nt][0] + bv.x + xv.x;
                rr.y = acc2[mt][nt][1] + bv.y + xv.y;
                *(float2*)(o + (size_t)n0 * DD + col) = rr;
            }
            if (n1 < N) {
                float2 xv = *(const float2*)(x + (size_t)n1 * DD + col);
                float2 rr;
                rr.x = acc2[mt][nt][2] + bv.x + xv.x;
                rr.y = acc2[mt][nt][3] + bv.y + xv.y;
                *(float2*)(o + (size_t)n1 * DD + col) = rr;
            }
        }
    }
}

// ---------------- block-diagonal cross attention (unchanged) ----------------
__global__ void attn_kernel(const float* __restrict__ x1,
                            const float* __restrict__ x2, int N) {
    int b = blockIdx.x;
    int dir = blockIdx.y;
    const float* rowsrc = dir ? x2 : x1;
    const float* colsrc = dir ? x1 : x2;
    float* att = g_att + (size_t)dir * N * DD;
    int rs = g_seg[(dir * NB + b) * 2 + 0];
    int re = g_seg[(dir * NB + b) * 2 + 1];
    int cs = g_seg[((1 - dir) * NB + b) * 2 + 0];
    int ce = g_seg[((1 - dir) * NB + b) * 2 + 1];
    const float* mean = g_colmeans + (1 - dir) * DD;

    int warp = threadIdx.x >> 5, lane = threadIdx.x & 31;

    for (int i = rs + warp; i < re; i += 8) {
        float4 a = *(const float4*)(rowsrc + (size_t)i * DD + lane * 4);
        float4 res;
        if (cs == ce) {
            float4 mv = *(const float4*)(mean + lane * 4);
            res.x = a.x - mv.x; res.y = a.y - mv.y;
            res.z = a.z - mv.z; res.w = a.w - mv.w;
        } else {
            float m = -3.4e38f;
            for (int j = cs; j < ce; ++j) {
                float4 bv = *(const float4*)(colsrc + (size_t)j * DD + lane * 4);
                float d = a.x * bv.x + a.y * bv.y + a.z * bv.z + a.w * bv.w;
                #pragma unroll
                for (int o = 16; o; o >>= 1) d += __shfl_xor_sync(0xffffffffu, d, o);
                m = fmaxf(m, d);
            }
            float se = 0.f;
            float4 acc = make_float4(0.f, 0.f, 0.f, 0.f);
            for (int j = cs; j < ce; ++j) {
                float4 bv = *(const float4*)(colsrc + (size_t)j * DD + lane * 4);
                float d = a.x * bv.x + a.y * bv.y + a.z * bv.z + a.w * bv.w;
                #pragma unroll
                for (int o = 16; o; o >>= 1) d += __shfl_xor_sync(0xffffffffu, d, o);
                float w = __expf(d - m);
                se += w;
                acc.x = fmaf(w, bv.x, acc.x);
                acc.y = fmaf(w, bv.y, acc.y);
                acc.z = fmaf(w, bv.z, acc.z);
                acc.w = fmaf(w, bv.w, acc.w);
            }
            float inv = 1.f / se;
            res.x = a.x - acc.x * inv; res.y = a.y - acc.y * inv;
            res.z = a.z - acc.z * inv; res.w = a.w - acc.w * inv;
        }
        *(float4*)(att + (size_t)i * DD + lane * 4) = res;
    }
}

// ---------------- launcher ----------------
extern "C" void kernel_launch(void* const* d_in, const int* in_sizes, int n_in,
                              void* d_out, int out_size) {
    const float* x1   = (const float*)d_in[0];
    const int*   ei1  = (const int*)d_in[1];
    const int*   bat1 = (const int*)d_in[2];
    const float* x2   = (const float*)d_in[3];
    const int*   ei2  = (const int*)d_in[4];
    const int*   bat2 = (const int*)d_in[5];
    const float* mW1 = (const float*)d_in[6];
    const float* mb1 = (const float*)d_in[7];
    const float* mW2 = (const float*)d_in[8];
    const float* mb2 = (const float*)d_in[9];
    const float* uW1 = (const float*)d_in[10];
    const float* ub1 = (const float*)d_in[11];
    const float* uW2 = (const float*)d_in[12];
    const float* ub2 = (const float*)d_in[13];
    float* out = (float*)d_out;

    int N = in_sizes[2];
    int E = in_sizes[1] / 2;

    cudaFuncSetAttribute(msg_mma_kernel, cudaFuncAttributeMaxDynamicSharedMemorySize, MSG_SMEM);
    cudaFuncSetAttribute(upd_mma_kernel, cudaFuncAttributeMaxDynamicSharedMemorySize, MSG_SMEM);

    int zn4 = 2 * N * HH / 4;
    zero_msgs_kernel<<<(zn4 + 255) / 256, 256>>>(zn4);
    seg_kernel<<<1, 128>>>(bat1, bat2, N);
    colmean_kernel<<<2, DD>>>(x1, x2, N);
    prep_all_kernel<<<1152, 256>>>(mW1, mW2, uW1, uW2);

    dim3 mgrid((E + 63) / 64, 2);
    msg_mma_kernel<<<mgrid, NTHR, MSG_SMEM>>>(x1, x2, ei1, ei2, mb1, mb2, N, E);

    attn_kernel<<<dim3(NB, 2), 256>>>(x1, x2, N);

    dim3 ugrid((N + 63) / 64, 2);
    upd_mma_kernel<<<ugrid, NTHR, MSG_SMEM>>>(x1, x2, ub1, ub2, out, N);
}

// round 10
// speedup vs baseline: 2.0242x; 1.0254x over previous
#include <cuda_runtime.h>
#include <cuda_bf16.h>
#include <math.h>
#include <stdint.h>

// ---------------- problem constants ----------------
#define DD      128
#define HH      256
#define MAXN    8192
#define NB      64
#define NTHR    512   // upd kernel threads
#define MTHR    256   // msg kernel threads

// scratch
__device__ float g_messages[2ull * MAXN * HH];
__device__ float g_att[2ull * MAXN * DD];
__device__ float g_colmeans[2 * DD];
__device__ int   g_seg[2 * NB * 2];

// msg weights: K=32 slices, row stride 80 B (32 data cols + 8 pad)
#define MB_SLICE 20480            // 256 n-rows * 80
__device__ __align__(16) unsigned char g_wtile[2][8][2][MB_SLICE];
// upd weights: K=64 slices, row stride 144 B
#define HCT_BYTES  36864
#define HCT2_BYTES 18432
__device__ __align__(16) unsigned char g_uw1[8][2][HCT_BYTES];
__device__ __align__(16) unsigned char g_uw2[4][2][HCT2_BYTES];

// ---------------- PTX helpers ----------------
__device__ __forceinline__ uint32_t smem_u32(const void* p) {
    uint32_t a;
    asm("{ .reg .u64 t; cvta.to.shared.u64 t, %1; cvt.u32.u64 %0, t; }" : "=r"(a) : "l"(p));
    return a;
}
__device__ __forceinline__ void cp_async16(unsigned int saddr, const void* gptr) {
    asm volatile("cp.async.cg.shared.global [%0], [%1], 16;" :: "r"(saddr), "l"(gptr));
}
__device__ __forceinline__ void cp_commit() { asm volatile("cp.async.commit_group;"); }
template<int N>
__device__ __forceinline__ void cp_wait() { asm volatile("cp.async.wait_group %0;" :: "n"(N)); }
__device__ __forceinline__ void red_add_v2(float* p, float a, float b) {
    asm volatile("red.global.add.v2.f32 [%0], {%1,%2};" :: "l"(p), "f"(a), "f"(b) : "memory");
}
__device__ __forceinline__ void ldmx4(uint32_t r[4], uint32_t addr) {
    asm volatile("ldmatrix.sync.aligned.m8n8.x4.shared.b16 {%0,%1,%2,%3}, [%4];"
        : "=r"(r[0]), "=r"(r[1]), "=r"(r[2]), "=r"(r[3]) : "r"(addr));
}
__device__ __forceinline__ void mma_bf16(float d[4], const uint32_t a[4],
                                         uint32_t b0, uint32_t b1) {
    asm volatile("mma.sync.aligned.m16n8k16.row.col.f32.bf16.bf16.f32 "
        "{%0,%1,%2,%3}, {%4,%5,%6,%7}, {%8,%9}, {%0,%1,%2,%3};"
        : "+f"(d[0]), "+f"(d[1]), "+f"(d[2]), "+f"(d[3])
        : "r"(a[0]), "r"(a[1]), "r"(a[2]), "r"(a[3]), "r"(b0), "r"(b1));
}
__device__ __forceinline__ uint32_t pk(__nv_bfloat16 a, __nv_bfloat16 b) {
    __nv_bfloat162 t = __halves2bfloat162(a, b);
    return *reinterpret_cast<uint32_t*>(&t);
}

// ---------------- tiny setup kernels ----------------
__global__ void zero_msgs_kernel(int n4) {
    int i = blockIdx.x * blockDim.x + threadIdx.x;
    if (i < n4) ((float4*)g_messages)[i] = make_float4(0.f, 0.f, 0.f, 0.f);
}

__global__ void seg_kernel(const int* __restrict__ b1, const int* __restrict__ b2, int N) {
    int t = threadIdx.x;
    if (t >= 2 * NB) return;
    int g = t / NB, b = t % NB;
    const int* arr = g ? b2 : b1;
    int lo = 0, hi = N;
    while (lo < hi) { int m = (lo + hi) >> 1; if (arr[m] < b) lo = m + 1; else hi = m; }
    int start = lo;
    lo = 0; hi = N;
    while (lo < hi) { int m = (lo + hi) >> 1; if (arr[m] <= b) lo = m + 1; else hi = m; }
    g_seg[t * 2 + 0] = start;
    g_seg[t * 2 + 1] = lo;
}

__global__ void colmean_kernel(const float* __restrict__ x1, const float* __restrict__ x2, int N) {
    const float* x = blockIdx.x ? x2 : x1;
    int c = threadIdx.x;
    float s0 = 0.f, s1 = 0.f, s2 = 0.f, s3 = 0.f;
    int r = 0;
    for (; r + 3 < N; r += 4) {
        s0 += x[(size_t)(r + 0) * DD + c];
        s1 += x[(size_t)(r + 1) * DD + c];
        s2 += x[(size_t)(r + 2) * DD + c];
        s3 += x[(size_t)(r + 3) * DD + c];
    }
    for (; r < N; ++r) s0 += x[(size_t)r * DD + c];
    g_colmeans[blockIdx.x * DD + c] = (s0 + s1 + s2 + s3) * (1.f / (float)N);
}

__device__ __forceinline__ void split_store(unsigned char* hdst, unsigned char* ldst,
                                            size_t off, float w) {
    __nv_bfloat16 h = __float2bfloat16(w);
    __nv_bfloat16 l = __float2bfloat16(w - __bfloat162float(h));
    *(__nv_bfloat16*)(hdst + off) = h;
    *(__nv_bfloat16*)(ldst + off) = l;
}

// merged weight prep
__global__ void prep_all_kernel(const float* __restrict__ mW1, const float* __restrict__ mW2,
                                const float* __restrict__ uW1, const float* __restrict__ uW2) {
    int idx = blockIdx.x * 256 + threadIdx.x;
    if (idx < 131072) {
        int layer = idx >> 16;
        int e = idx & 65535;
        int k = e >> 8, n = e & 255;
        const float* W = layer ? mW2 : mW1;
        split_store(g_wtile[layer][k >> 5][0], g_wtile[layer][k >> 5][1],
                    (size_t)n * 80 + (size_t)(k & 31) * 2, W[e]);
    } else if (idx < 262144) {
        int e = idx - 131072;
        int k = e >> 8, n = e & 255;
        split_store(g_uw1[k >> 6][0], g_uw1[k >> 6][1],
                    (size_t)n * 144 + (size_t)(k & 63) * 2, uW1[e]);
    } else {
        int e = idx - 262144;
        int k = e >> 7, n = e & 127;
        split_store(g_uw2[k >> 6][0], g_uw2[k >> 6][1],
                    (size_t)n * 144 + (size_t)(k & 63) * 2, uW2[e]);
    }
}

// ================= msg kernel (256 thr, occ 2) =================
// SMEM: A_hi [64][264]bf16 (stride 528B), A_lo, B slice (hi 20480 + lo 20480), ids
#define MA_STRIDE 528
#define MOFF_AH 0
#define MOFF_AL 33792
#define MOFF_B  67584
#define MOFF_ID 108544
#define MSG_SMEM2 (108544 + 512)

__device__ __forceinline__ void load_msg_b(uint32_t sb, int tid, int layer, int s) {
    const unsigned char* hs = g_wtile[layer][s][0];
    const unsigned char* ls = g_wtile[layer][s][1];
    #pragma unroll
    for (int t = 0; t < 5; ++t) {
        int i = tid + t * MTHR;
        cp_async16(sb + MOFF_B + i * 16, hs + i * 16);
        cp_async16(sb + MOFF_B + MB_SLICE + i * 16, ls + i * 16);
    }
    cp_commit();
}

// convert 64 fp32 cols of row r into hi/lo A tile at col base cb
__device__ __forceinline__ void gather64(char* smc, int r, int cb, const float* __restrict__ rowp) {
    #pragma unroll
    for (int b = 0; b < 4; ++b) {
        const float4* p = (const float4*)(rowp + b * 16);
        uint32_t hi[8], lo[8];
        #pragma unroll
        for (int q = 0; q < 4; ++q) {
            float4 v = p[q];
            __nv_bfloat16 h0 = __float2bfloat16(v.x), h1 = __float2bfloat16(v.y);
            __nv_bfloat16 h2 = __float2bfloat16(v.z), h3 = __float2bfloat16(v.w);
            hi[q * 2 + 0] = pk(h0, h1);
            hi[q * 2 + 1] = pk(h2, h3);
            lo[q * 2 + 0] = pk(__float2bfloat16(v.x - __bfloat162float(h0)),
                               __float2bfloat16(v.y - __bfloat162float(h1)));
            lo[q * 2 + 1] = pk(__float2bfloat16(v.z - __bfloat162float(h2)),
                               __float2bfloat16(v.w - __bfloat162float(h3)));
        }
        uint4* dh = (uint4*)(smc + MOFF_AH + r * MA_STRIDE + (cb + b * 16) * 2);
        uint4* dl = (uint4*)(smc + MOFF_AL + r * MA_STRIDE + (cb + b * 16) * 2);
        dh[0] = make_uint4(hi[0], hi[1], hi[2], hi[3]);
        dh[1] = make_uint4(hi[4], hi[5], hi[6], hi[7]);
        dl[0] = make_uint4(lo[0], lo[1], lo[2], lo[3]);
        dl[1] = make_uint4(lo[4], lo[5], lo[6], lo[7]);
    }
}

// one K=32 slice mma pass; A k-base = s*32; warp tile 32 rows x 64 cols
__device__ __forceinline__ void mma_slice(uint32_t sb, int kbase,
                                          int wm, int wn, int lane, float acc[2][8][4]) {
    #pragma unroll
    for (int ks = 0; ks < 2; ++ks) {
        int kg = kbase + ks * 16;
        uint32_t ah[2][4], al[2][4];
        #pragma unroll
        for (int mt = 0; mt < 2; ++mt) {
            int row = wm * 32 + mt * 16 + (lane & 15);
            uint32_t addr = sb + MOFF_AH + row * MA_STRIDE + (kg + (lane >> 4) * 8) * 2;
            ldmx4(ah[mt], addr);
            ldmx4(al[mt], addr + (MOFF_AL - MOFF_AH));
        }
        #pragma unroll
        for (int ntp = 0; ntp < 4; ++ntp) {
            int q = lane >> 3, rr = lane & 7;
            int n = wn * 64 + ntp * 16 + (q >> 1) * 8 + rr;
            uint32_t baddr = sb + MOFF_B + n * 80 + (ks * 16 + (q & 1) * 8) * 2;
            uint32_t bh[4], bl[4];
            ldmx4(bh, baddr);
            ldmx4(bl, baddr + MB_SLICE);
            #pragma unroll
            for (int mt = 0; mt < 2; ++mt) {
                mma_bf16(acc[mt][ntp * 2],     ah[mt], bh[0], bh[1]);
                mma_bf16(acc[mt][ntp * 2],     ah[mt], bl[0], bl[1]);
                mma_bf16(acc[mt][ntp * 2],     al[mt], bh[0], bh[1]);
                mma_bf16(acc[mt][ntp * 2 + 1], ah[mt], bh[2], bh[3]);
                mma_bf16(acc[mt][ntp * 2 + 1], ah[mt], bl[2], bl[3]);
                mma_bf16(acc[mt][ntp * 2 + 1], al[mt], bh[2], bh[3]);
            }
        }
    }
}

__global__ void __launch_bounds__(MTHR, 2)
msg_mma_kernel(const float* __restrict__ x1, const float* __restrict__ x2,
               const int* __restrict__ ei1, const int* __restrict__ ei2,
               const float* __restrict__ b1, const float* __restrict__ b2,
               int N, int E) {
    int g = blockIdx.y;
    const float* x = g ? x2 : x1;
    const int* ei = g ? ei2 : ei1;
    float* messages = g_messages + (size_t)g * N * HH;

    extern __shared__ char smc[];
    uint32_t sb = smem_u32(smc);
    int* s_src = (int*)(smc + MOFF_ID);
    int* s_tgt = s_src + 64;

    int tid = threadIdx.x, wid = tid >> 5, lane = tid & 31;
    int base = blockIdx.x * 64;

    if (tid < 64) {
        int e = base + tid;
        s_tgt[tid] = (e < E) ? ei[e] : 0;
        s_src[tid] = (e < E) ? ei[E + e] : 0;
    }
    __syncthreads();

    int wm = wid & 1, wn = wid >> 1;     // 2 row blocks x 4 col blocks (64 cols)
    int gr = lane >> 2, gc = lane & 3;

    // issue B slice 0 load, then gather A (cols 0-127 = x_src, 128-255 = x_tgt)
    load_msg_b(sb, tid, 0, 0);
    {
        int r = tid >> 2, seg = tid & 3;
        const float* rowp = (seg < 2) ? (x + (size_t)s_src[r] * DD + seg * 64)
                                      : (x + (size_t)s_tgt[r] * DD + (seg - 2) * 64);
        gather64(smc, r, seg * 64, rowp);
    }
    cp_wait<0>();
    __syncthreads();

    float acc[2][8][4];
    #pragma unroll
    for (int mt = 0; mt < 2; ++mt)
        #pragma unroll
        for (int nt = 0; nt < 8; ++nt)
            #pragma unroll
            for (int q = 0; q < 4; ++q) acc[mt][nt][q] = 0.f;

    // -------- layer 1: K=256 in 8 slices --------
    for (int s = 0; s < 8; ++s) {
        mma_slice(sb, s * 32, wm, wn, lane, acc);
        __syncthreads();
        if (s < 7) {
            load_msg_b(sb, tid, 0, s + 1);
            cp_wait<0>();
            __syncthreads();
        }
    }

    // epilogue 1: bias + relu + split -> overwrite A tiles with H; load layer-2 slice 0
    load_msg_b(sb, tid, 1, 0);
    #pragma unroll
    for (int nt = 0; nt < 8; ++nt) {
        int col = wn * 64 + nt * 8 + 2 * gc;
        float2 bv = *(const float2*)(b1 + col);
        #pragma unroll
        for (int mt = 0; mt < 2; ++mt) {
            float f0 = fmaxf(acc[mt][nt][0] + bv.x, 0.f);
            float f1 = fmaxf(acc[mt][nt][1] + bv.y, 0.f);
            float f2 = fmaxf(acc[mt][nt][2] + bv.x, 0.f);
            float f3 = fmaxf(acc[mt][nt][3] + bv.y, 0.f);
            __nv_bfloat16 h0 = __float2bfloat16(f0), h1 = __float2bfloat16(f1);
            __nv_bfloat16 h2 = __float2bfloat16(f2), h3 = __float2bfloat16(f3);
            int r0 = wm * 32 + mt * 16 + gr;
            *(uint32_t*)(smc + MOFF_AH + r0 * MA_STRIDE + col * 2) = pk(h0, h1);
            *(uint32_t*)(smc + MOFF_AL + r0 * MA_STRIDE + col * 2) =
                pk(__float2bfloat16(f0 - __bfloat162float(h0)),
                   __float2bfloat16(f1 - __bfloat162float(h1)));
            *(uint32_t*)(smc + MOFF_AH + (r0 + 8) * MA_STRIDE + col * 2) = pk(h2, h3);
            *(uint32_t*)(smc + MOFF_AL + (r0 + 8) * MA_STRIDE + col * 2) =
                pk(__float2bfloat16(f2 - __bfloat162float(h2)),
                   __float2bfloat16(f3 - __bfloat162float(h3)));
            acc[mt][nt][0] = acc[mt][nt][1] = acc[mt][nt][2] = acc[mt][nt][3] = 0.f;
        }
    }
    cp_wait<0>();
    __syncthreads();

    // -------- layer 2: K=256 in 8 slices --------
    for (int s = 0; s < 8; ++s) {
        mma_slice(sb, s * 32, wm, wn, lane, acc);
        __syncthreads();
        if (s < 7) {
            load_msg_b(sb, tid, 1, s + 1);
            cp_wait<0>();
            __syncthreads();
        }
    }

    // scatter-add into messages[tgt]
    #pragma unroll
    for (int mt = 0; mt < 2; ++mt) {
        int r0 = wm * 32 + mt * 16 + gr;
        int r1 = r0 + 8;
        bool v0 = (base + r0) < E, v1 = (base + r1) < E;
        float* m0 = messages + (size_t)s_tgt[r0] * HH;
        float* m1 = messages + (size_t)s_tgt[r1] * HH;
        #pragma unroll
        for (int nt = 0; nt < 8; ++nt) {
            int col = wn * 64 + nt * 8 + 2 * gc;
            float2 bv = *(const float2*)(b2 + col);
            if (v0) red_add_v2(m0 + col, acc[mt][nt][0] + bv.x, acc[mt][nt][1] + bv.y);
            if (v1) red_add_v2(m1 + col, acc[mt][nt][2] + bv.x, acc[mt][nt][3] + bv.y);
        }
    }
}

// ================= upd kernel (unchanged from round 9) =================
#define OFF_AH 0
#define OFF_AL 17408
#define OFF_B  34816
#define BBUF_BYTES 73728
#define OFF_ID (34816 + 2*BBUF_BYTES)
#define UPD_SMEM (OFF_ID + 1024)

__device__ __forceinline__ void gather_a(char* smc, int r, int seg, const float* __restrict__ rowp) {
    const float4* row = (const float4*)(rowp + seg * 16);
    uint32_t hi[8], lo[8];
    #pragma unroll
    for (int q = 0; q < 4; ++q) {
        float4 v = row[q];
        __nv_bfloat16 h0 = __float2bfloat16(v.x), h1 = __float2bfloat16(v.y);
        __nv_bfloat16 h2 = __float2bfloat16(v.z), h3 = __float2bfloat16(v.w);
        hi[q * 2 + 0] = pk(h0, h1);
        hi[q * 2 + 1] = pk(h2, h3);
        lo[q * 2 + 0] = pk(__float2bfloat16(v.x - __bfloat162float(h0)),
                           __float2bfloat16(v.y - __bfloat162float(h1)));
        lo[q * 2 + 1] = pk(__float2bfloat16(v.z - __bfloat162float(h2)),
                           __float2bfloat16(v.w - __bfloat162float(h3)));
    }
    uint4* dh = (uint4*)(smc + OFF_AH + r * 272 + seg * 32);
    uint4* dl = (uint4*)(smc + OFF_AL + r * 272 + seg * 32);
    dh[0] = make_uint4(hi[0], hi[1], hi[2], hi[3]);
    dh[1] = make_uint4(hi[4], hi[5], hi[6], hi[7]);
    dl[0] = make_uint4(lo[0], lo[1], lo[2], lo[3]);
    dl[1] = make_uint4(lo[4], lo[5], lo[6], lo[7]);
}

template<int NT>
__device__ __forceinline__ void mma_hc(uint32_t sb, int a_k0, uint32_t b_base,
                                       int wm, int wn, int lane, float acc[2][NT][4]) {
    #pragma unroll
    for (int ks = 0; ks < 4; ++ks) {
        int k0 = ks * 16;
        uint32_t ah[2][4], al[2][4];
        #pragma unroll
        for (int mt = 0; mt < 2; ++mt) {
            int row = wm * 32 + mt * 16 + (lane & 15);
            uint32_t addr = sb + OFF_AH + row * 272 + (a_k0 + k0 + (lane >> 4) * 8) * 2;
            ldmx4(ah[mt], addr);
            ldmx4(al[mt], addr + (OFF_AL - OFF_AH));
        }
        uint32_t bh[(NT + 1) / 2][4], bl[(NT + 1) / 2][4];
        #pragma unroll
        for (int ntp = 0; ntp < (NT + 1) / 2; ++ntp) {
            int q = lane >> 3, rr = lane & 7;
            int n = wn * (NT * 8) + ntp * 16 + (q >> 1) * 8 + rr;
            int kk = k0 + (q & 1) * 8;
            uint32_t addr = b_base + n * 144 + kk * 2;
            ldmx4(bh[ntp], addr);
            ldmx4(bl[ntp], addr + HCT_BYTES);
        }
        #pragma unroll
        for (int mt = 0; mt < 2; ++mt)
            #pragma unroll
            for (int nt = 0; nt < NT; ++nt) {
                int p = nt >> 1, h2 = (nt & 1) * 2;
                mma_bf16(acc[mt][nt], ah[mt], bh[p][h2], bh[p][h2 + 1]);
                mma_bf16(acc[mt][nt], ah[mt], bl[p][h2], bl[p][h2 + 1]);
                mma_bf16(acc[mt][nt], al[mt], bh[p][h2], bh[p][h2 + 1]);
            }
    }
}

__device__ __forceinline__ void load_b_hc(uint32_t b_base, int tid,
                                          const unsigned char* hsrc,
                                          const unsigned char* lsrc, int lines) {
    for (int t = tid; t < lines; t += NTHR) {
        cp_async16(b_base + t * 16, hsrc + t * 16);
        cp_async16(b_base + HCT_BYTES + t * 16, lsrc + t * 16);
    }
    cp_commit();
}

__global__ void __launch_bounds__(NTHR, 1)
upd_mma_kernel(const float* __restrict__ x1, const float* __restrict__ x2,
               const float* __restrict__ b1u, const float* __restrict__ b2u,
               float* __restrict__ out, int N) {
    int g = blockIdx.y;
    const float* x = g ? x2 : x1;
    const float* messages = g_messages + (size_t)g * N * HH;
    const float* att = g_att + (size_t)g * N * DD;
    float* o = out + (size_t)g * N * DD;

    extern __shared__ char smc[];
    uint32_t sb = smem_u32(smc);

    int tid = threadIdx.x, wid = tid >> 5, lane = tid & 31;
    int base = blockIdx.x * 64;
    int wm = wid & 1, wn = wid >> 1;
    int gr = lane >> 2, gc = lane & 3;
    int r = tid >> 3, seg = tid & 7;
    uint32_t bbuf[2] = { sb + OFF_B, sb + OFF_B + BBUF_BYTES };

    int node = base + r;
    if (node >= N) node = N - 1;
    const float* srcs[4] = {
        messages + (size_t)node * HH,
        messages + (size_t)node * HH + 128,
        att + (size_t)node * DD,
        x + (size_t)node * DD
    };

    float acc[2][4][4];
    #pragma unroll
    for (int mt = 0; mt < 2; ++mt)
        #pragma unroll
        for (int nt = 0; nt < 4; ++nt)
            #pragma unroll
            for (int q = 0; q < 4; ++q) acc[mt][nt][q] = 0.f;

    load_b_hc(bbuf[0], tid, g_uw1[0][0], g_uw1[0][1], 2304);
    gather_a(smc, r, seg, srcs[0]);
    load_b_hc(bbuf[1], tid, g_uw1[1][0], g_uw1[1][1], 2304);
    cp_wait<1>();
    __syncthreads();

    #pragma unroll
    for (int hc = 0; hc < 8; ++hc) {
        mma_hc<4>(sb, (hc & 1) * 64, bbuf[hc & 1], wm, wn, lane, acc);
        __syncthreads();
        if ((hc & 1) == 1 && hc < 7) gather_a(smc, r, seg, srcs[(hc + 1) >> 1]);
        if (hc + 2 < 8) {
            load_b_hc(bbuf[hc & 1], tid, g_uw1[hc + 2][0], g_uw1[hc + 2][1], 2304);
            cp_wait<1>();
        } else if (hc + 1 < 8) {
            cp_wait<0>();
        }
        __syncthreads();
    }

    uint32_t hh[2][4][2], hl[2][4][2];
    #pragma unroll
    for (int nt = 0; nt < 4; ++nt) {
        int col = wn * 32 + nt * 8 + 2 * gc;
        float2 bv = *(const float2*)(b1u + col);
        #pragma unroll
        for (int mt = 0; mt < 2; ++mt) {
            float f0 = fmaxf(acc[mt][nt][0] + bv.x, 0.f);
            float f1 = fmaxf(acc[mt][nt][1] + bv.y, 0.f);
            float f2 = fmaxf(acc[mt][nt][2] + bv.x, 0.f);
            float f3 = fmaxf(acc[mt][nt][3] + bv.y, 0.f);
            __nv_bfloat16 h0 = __float2bfloat16(f0), h1 = __float2bfloat16(f1);
            __nv_bfloat16 h2 = __float2bfloat16(f2), h3 = __float2bfloat16(f3);
            hh[mt][nt][0] = pk(h0, h1);
            hh[mt][nt][1] = pk(h2, h3);
            hl[mt][nt][0] = pk(__float2bfloat16(f0 - __bfloat162float(h0)),
                               __float2bfloat16(f1 - __bfloat162float(h1)));
            hl[mt][nt][1] = pk(__float2bfloat16(f2 - __bfloat162float(h2)),
                               __float2bfloat16(f3 - __bfloat162float(h3)));
            acc[mt][nt][0] = acc[mt][nt][1] = acc[mt][nt][2] = acc[mt][nt][3] = 0.f;
        }
    }

    int wm2 = wid & 1, wn2 = wid >> 1;
    float (*acc2)[2][4] = (float (*)[2][4])acc;

    load_b_hc(bbuf[0], tid, g_uw2[0][0], g_uw2[0][1], 1152);
    if (wn < 4) {
        #pragma unroll
        for (int mt = 0; mt < 2; ++mt) {
            int rr = wm * 32 + mt * 16 + gr;
            #pragma unroll
            for (int nt = 0; nt < 4; ++nt) {
                int cc = wn * 32 + nt * 8 + 2 * gc;
                *(uint32_t*)(smc + OFF_AH + rr * 272 + cc * 2)       = hh[mt][nt][0];
                *(uint32_t*)(smc + OFF_AL + rr * 272 + cc * 2)       = hl[mt][nt][0];
                *(uint32_t*)(smc + OFF_AH + (rr + 8) * 272 + cc * 2) = hh[mt][nt][1];
                *(uint32_t*)(smc + OFF_AL + (rr + 8) * 272 + cc * 2) = hl[mt][nt][1];
            }
        }
    }
    load_b_hc(bbuf[1], tid, g_uw2[1][0], g_uw2[1][1], 1152);
    cp_wait<1>();
    __syncthreads();

    #pragma unroll
    for (int hc = 0; hc < 4; ++hc) {
        mma_hc<2>(sb, (hc & 1) * 64, bbuf[hc & 1], wm2, wn2, lane, acc2);
        __syncthreads();
        if (hc == 1 && wn >= 4) {
            #pragma unroll
            for (int mt = 0; mt < 2; ++mt) {
                int rr = wm * 32 + mt * 16 + gr;
                #pragma unroll
                for (int nt = 0; nt < 4; ++nt) {
                    int cc = (wn & 3) * 32 + nt * 8 + 2 * gc;
                    *(uint32_t*)(smc + OFF_AH + rr * 272 + cc * 2)       = hh[mt][nt][0];
                    *(uint32_t*)(smc + OFF_AL + rr * 272 + cc * 2)       = hl[mt][nt][0];
                    *(uint32_t*)(smc + OFF_AH + (rr + 8) * 272 + cc * 2) = hh[mt][nt][1];
                    *(uint32_t*)(smc + OFF_AL + (rr + 8) * 272 + cc * 2) = hl[mt][nt][1];
                }
            }
        }
        if (hc + 2 < 4) {
            load_b_hc(bbuf[hc & 1], tid, g_uw2[hc + 2][0], g_uw2[hc + 2][1], 1152);
            cp_wait<1>();
        } else if (hc + 1 < 4) {
            cp_wait<0>();
        }
        __syncthreads();
    }

    #pragma unroll
    for (int mt = 0; mt < 2; ++mt) {
        int r0 = wm2 * 32 + mt * 16 + gr;
        int r1 = r0 + 8;
        int n0 = base + r0, n1 = base + r1;
        #pragma unroll
        for (int nt = 0; nt < 2; ++nt) {
            int col = wn2 * 16 + nt * 8 + 2 * gc;
            float2 bv = *(const float2*)(b2u + col);
            if (n0 < N) {
                float2 xv = *(const float2*)(x + (size_t)n0 * DD + col);
                float2 rr;
                rr.x = acc2[mt][nt][0] + bv.x + xv.x;
                rr.y = acc2[mt][nt][1] + bv.y + xv.y;
                *(float2*)(o + (size_t)n0 * DD + col) = rr;
            }
            if (n1 < N) {
                float2 xv = *(const float2*)(x + (size_t)n1 * DD + col);
                float2 rr;
                rr.x = acc2[mt][nt][2] + bv.x + xv.x;
                rr.y = acc2[mt][nt][3] + bv.y + xv.y;
                *(float2*)(o + (size_t)n1 * DD + col) = rr;
            }
        }
    }
}

// ---------------- block-diagonal cross attention (unchanged) ----------------
__global__ void attn_kernel(const float* __restrict__ x1,
                            const float* __restrict__ x2, int N) {
    int b = blockIdx.x;
    int dir = blockIdx.y;
    const float* rowsrc = dir ? x2 : x1;
    const float* colsrc = dir ? x1 : x2;
    float* att = g_att + (size_t)dir * N * DD;
    int rs = g_seg[(dir * NB + b) * 2 + 0];
    int re = g_seg[(dir * NB + b) * 2 + 1];
    int cs = g_seg[((1 - dir) * NB + b) * 2 + 0];
    int ce = g_seg[((1 - dir) * NB + b) * 2 + 1];
    const float* mean = g_colmeans + (1 - dir) * DD;

    int warp = threadIdx.x >> 5, lane = threadIdx.x & 31;

    for (int i = rs + warp; i < re; i += 8) {
        float4 a = *(const float4*)(rowsrc + (size_t)i * DD + lane * 4);
        float4 res;
        if (cs == ce) {
            float4 mv = *(const float4*)(mean + lane * 4);
            res.x = a.x - mv.x; res.y = a.y - mv.y;
            res.z = a.z - mv.z; res.w = a.w - mv.w;
        } else {
            float m = -3.4e38f;
            for (int j = cs; j < ce; ++j) {
                float4 bv = *(const float4*)(colsrc + (size_t)j * DD + lane * 4);
                float d = a.x * bv.x + a.y * bv.y + a.z * bv.z + a.w * bv.w;
                #pragma unroll
                for (int o = 16; o; o >>= 1) d += __shfl_xor_sync(0xffffffffu, d, o);
                m = fmaxf(m, d);
            }
            float se = 0.f;
            float4 acc = make_float4(0.f, 0.f, 0.f, 0.f);
            for (int j = cs; j < ce; ++j) {
                float4 bv = *(const float4*)(colsrc + (size_t)j * DD + lane * 4);
                float d = a.x * bv.x + a.y * bv.y + a.z * bv.z + a.w * bv.w;
                #pragma unroll
                for (int o = 16; o; o >>= 1) d += __shfl_xor_sync(0xffffffffu, d, o);
                float w = __expf(d - m);
                se += w;
                acc.x = fmaf(w, bv.x, acc.x);
                acc.y = fmaf(w, bv.y, acc.y);
                acc.z = fmaf(w, bv.z, acc.z);
                acc.w = fmaf(w, bv.w, acc.w);
            }
            float inv = 1.f / se;
            res.x = a.x - acc.x * inv; res.y = a.y - acc.y * inv;
            res.z = a.z - acc.z * inv; res.w = a.w - acc.w * inv;
        }
        *(float4*)(att + (size_t)i * DD + lane * 4) = res;
    }
}

// ---------------- launcher ----------------
extern "C" void kernel_launch(void* const* d_in, const int* in_sizes, int n_in,
                              void* d_out, int out_size) {
    const float* x1   = (const float*)d_in[0];
    const int*   ei1  = (const int*)d_in[1];
    const int*   bat1 = (const int*)d_in[2];
    const float* x2   = (const float*)d_in[3];
    const int*   ei2  = (const int*)d_in[4];
    const int*   bat2 = (const int*)d_in[5];
    const float* mW1 = (const float*)d_in[6];
    const float* mb1 = (const float*)d_in[7];
    const float* mW2 = (const float*)d_in[8];
    const float* mb2 = (const float*)d_in[9];
    const float* uW1 = (const float*)d_in[10];
    const float* ub1 = (const float*)d_in[11];
    const float* uW2 = (const float*)d_in[12];
    const float* ub2 = (const float*)d_in[13];
    float* out = (float*)d_out;

    int N = in_sizes[2];
    int E = in_sizes[1] / 2;

    cudaFuncSetAttribute(msg_mma_kernel, cudaFuncAttributeMaxDynamicSharedMemorySize, MSG_SMEM2);
    cudaFuncSetAttribute(upd_mma_kernel, cudaFuncAttributeMaxDynamicSharedMemorySize, UPD_SMEM);

    int zn4 = 2 * N * HH / 4;
    zero_msgs_kernel<<<(zn4 + 255) / 256, 256>>>(zn4);
    seg_kernel<<<1, 128>>>(bat1, bat2, N);
    colmean_kernel<<<2, DD>>>(x1, x2, N);
    prep_all_kernel<<<1152, 256>>>(mW1, mW2, uW1, uW2);

    dim3 mgrid((E + 63) / 64, 2);
    msg_mma_kernel<<<mgrid, MTHR, MSG_SMEM2>>>(x1, x2, ei1, ei2, mb1, mb2, N, E);

    attn_kernel<<<dim3(NB, 2), 256>>>(x1, x2, N);

    dim3 ugrid((N + 63) / 64, 2);
    upd_mma_kernel<<<ugrid, NTHR, UPD_SMEM>>>(x1, x2, ub1, ub2, out, N);
}